// round 12
// baseline (speedup 1.0000x reference)
#include <cuda_runtime.h>
#include <cuda_bf16.h>
#include <cstdint>

#define NB 192
#define SS 512
#define EE 128
#define NROWS (NB*SS)

// ---------------- scratch (bytes) ----------------
#define B_MAT ((size_t)NROWS*EE*2)          // bf16 [NROWS,128]
#define O_Q_HI   ((size_t)0)
#define O_Q_LO   (O_Q_HI + B_MAT)
#define O_K_HI   (O_Q_LO + B_MAT)
#define O_K_LO   (O_K_HI + B_MAT)
#define O_VT_HI  (O_K_LO + B_MAT)
#define O_VT_LO  (O_VT_HI + B_MAT)
#define O_ATTO   (O_VT_LO + B_MAT)                    // fp32 attn out
#define O_W_HI   (O_ATTO + (size_t)NROWS*EE*4)
#define O_W_LO   (O_W_HI + (size_t)4*EE*EE*2)
#define O_RS     (O_W_LO + (size_t)4*EE*EE*2)
#define O_MB     (O_RS + (size_t)NROWS*4)             // adj bitmasks, 64 B/row
#define SCRATCH_BYTES (O_MB + (size_t)NROWS*64)

__device__ __align__(1024) char g_scratch[SCRATCH_BYTES];

// ---------------- SMEM layouts ----------------
#define MM_AH 0
#define MM_AL 16384
#define MM_WH 32768
#define MM_WL 65536
#define MM_SMEM 98304
#define F_QH 0
#define F_QL 16384
#define F_KH 32768
#define F_KL 49152
#define F_PH 65536
#define F_PL 73728
#define F_VH 81920
#define F_VL 90112
#define F_STAT 98304
#define F_SMEM (98304 + 1024)

__device__ __forceinline__ uint32_t smem_u32(const void* p) {
    uint32_t a;
    asm("{ .reg .u64 t; cvta.to.shared.u64 t, %1; cvt.u32.u64 %0, t; }" : "=r"(a) : "l"(p));
    return a;
}

__device__ __forceinline__ uint32_t sw_off(int row, int chunk) {
    return (uint32_t)(row * 256 + ((chunk ^ (row & 7)) << 4));
}
__device__ __forceinline__ uint32_t sw_off128(int row, int chunk) {
    return (uint32_t)(row * 128 + ((chunk ^ (row & 7)) << 4));
}

#define CP_COMMIT() asm volatile("cp.async.commit_group;" ::: "memory")
#define CP_WAIT0()  asm volatile("cp.async.wait_group 0;" ::: "memory")
#define CP_WAIT1()  asm volatile("cp.async.wait_group 1;" ::: "memory")

__device__ __forceinline__ void cp16(char* dst, const void* src) {
    uint32_t d = smem_u32(dst);
    asm volatile("cp.async.cg.shared.global [%0], [%1], 16;" :: "r"(d), "l"(src));
}

template <int ROWS>
__device__ __forceinline__ void cp_tile256(char* dst, const __nv_bfloat16* g, int pitch) {
    #pragma unroll
    for (int it = 0; it < ROWS / 8; it++) {
        int idx = threadIdx.x + it * 128;
        int row = idx >> 4, ch = idx & 15;
        cp16(dst + sw_off(row, ch), g + (size_t)row * pitch + ch * 8);
    }
}
__device__ __forceinline__ void cp_tile128_64(char* dst, const __nv_bfloat16* g, int pitch) {
    #pragma unroll
    for (int it = 0; it < 4; it++) {
        int idx = threadIdx.x + it * 128;
        int row = idx >> 3, ch = idx & 7;
        cp16(dst + sw_off128(row, ch), g + (size_t)row * pitch + ch * 8);
    }
}

__device__ __forceinline__ void ldsm4(uint32_t* r, uint32_t a) {
    asm volatile("ldmatrix.sync.aligned.m8n8.x4.shared.b16 {%0,%1,%2,%3}, [%4];"
                 : "=r"(r[0]), "=r"(r[1]), "=r"(r[2]), "=r"(r[3]) : "r"(a));
}
__device__ __forceinline__ void mma_bf16(float* c, const uint32_t* a, const uint32_t* b) {
    asm volatile(
        "mma.sync.aligned.m16n8k16.row.col.f32.bf16.bf16.f32 "
        "{%0,%1,%2,%3},{%4,%5,%6,%7},{%8,%9},{%0,%1,%2,%3};"
        : "+f"(c[0]), "+f"(c[1]), "+f"(c[2]), "+f"(c[3])
        : "r"(a[0]), "r"(a[1]), "r"(a[2]), "r"(a[3]), "r"(b[0]), "r"(b[1]));
}

__device__ __forceinline__ void split_bf16(float v, __nv_bfloat16& h, __nv_bfloat16& l) {
    h = __float2bfloat16(v);
    l = __float2bfloat16(v - __bfloat162float(h));
}
__device__ __forceinline__ uint32_t pack2(float a, float b) {
    __nv_bfloat162 t = __floats2bfloat162_rn(a, b);
    return *reinterpret_cast<uint32_t*>(&t);
}

// ---- LN(no affine)+ReLU+split of 64 fp32 rows -> swizzled hi/lo tiles ----
__device__ __forceinline__ void ln_stage(const float* __restrict__ src,
                                         char* dsth, char* dstl) {
    int lane = threadIdx.x & 31, wid = threadIdx.x >> 5;
    #pragma unroll
    for (int r = 0; r < 16; r++) {
        int row = wid * 16 + r;
        float4 a = reinterpret_cast<const float4*>(src + (size_t)row * EE)[lane];
        float s = a.x + a.y + a.z + a.w;
        float q = a.x * a.x + a.y * a.y + a.z * a.z + a.w * a.w;
        #pragma unroll
        for (int o = 16; o; o >>= 1) {
            s += __shfl_xor_sync(0xffffffffu, s, o);
            q += __shfl_xor_sync(0xffffffffu, q, o);
        }
        float mean = s * (1.0f / 128.0f);
        float var  = q * (1.0f / 128.0f) - mean * mean;
        float inv  = rsqrtf(var + 1e-5f);
        float r0 = fmaxf((a.x - mean) * inv, 0.f);
        float r1 = fmaxf((a.y - mean) * inv, 0.f);
        float r2 = fmaxf((a.z - mean) * inv, 0.f);
        float r3 = fmaxf((a.w - mean) * inv, 0.f);
        __nv_bfloat16 h0, l0, h1, l1, h2, l2, h3, l3;
        split_bf16(r0, h0, l0); split_bf16(r1, h1, l1);
        split_bf16(r2, h2, l2); split_bf16(r3, h3, l3);
        uint2 uh, ul;
        uh.x = pack2(__bfloat162float(h0), __bfloat162float(h1));
        uh.y = pack2(__bfloat162float(h2), __bfloat162float(h3));
        ul.x = pack2(__bfloat162float(l0), __bfloat162float(l1));
        ul.y = pack2(__bfloat162float(l2), __bfloat162float(l3));
        uint32_t off = sw_off(row, lane >> 1) + (lane & 1) * 8;
        *reinterpret_cast<uint2*>(dsth + off) = uh;
        *reinterpret_cast<uint2*>(dstl + off) = ul;
    }
}

// ---- x3 MMA, fragment-reuse: A 64-row(256B), B 128-row(256B); 4 warps 32x64
__device__ __forceinline__ void mma_mm_x3(float acc[2][8][4],
                                          uint32_t sAh, uint32_t sAl,
                                          uint32_t sBh, uint32_t sBl) {
    int lane = threadIdx.x & 31, wid = threadIdx.x >> 5;
    int wm = (wid & 1) * 32, wn = (wid >> 1) * 64;
    int rsub  = ((lane >> 3) & 1) * 8 + (lane & 7);
    int khalf = (lane >> 4) & 1;
    #pragma unroll
    for (int ks = 0; ks < 8; ks++) {
        int chunk = 2 * ks + khalf;
        uint32_t ah[2][4], al[2][4];
        #pragma unroll
        for (int mt = 0; mt < 2; mt++) {
            uint32_t o = sw_off(wm + mt * 16 + rsub, chunk);
            ldsm4(ah[mt], sAh + o);
            ldsm4(al[mt], sAl + o);
        }
        uint32_t bh[8][2], bl[8][2];
        #pragma unroll
        for (int nt2 = 0; nt2 < 4; nt2++) {
            uint32_t o = sw_off(wn + nt2 * 16 + rsub, chunk);
            uint32_t r[4];
            ldsm4(r, sBh + o);
            bh[nt2 * 2][0] = r[0]; bh[nt2 * 2 + 1][0] = r[1];
            bh[nt2 * 2][1] = r[2]; bh[nt2 * 2 + 1][1] = r[3];
            ldsm4(r, sBl + o);
            bl[nt2 * 2][0] = r[0]; bl[nt2 * 2 + 1][0] = r[1];
            bl[nt2 * 2][1] = r[2]; bl[nt2 * 2 + 1][1] = r[3];
        }
        #pragma unroll
        for (int mt = 0; mt < 2; mt++)
            #pragma unroll
            for (int nt = 0; nt < 8; nt++) {
                mma_bf16(acc[mt][nt], ah[mt], bh[nt]);
                mma_bf16(acc[mt][nt], al[mt], bh[nt]);
                mma_bf16(acc[mt][nt], ah[mt], bl[nt]);
            }
    }
}

// ---- x3 MMA, fragment-reuse for S: 64x64 K=128; 4 warps 32x32
__device__ __forceinline__ void mma_s_x3(float acc[2][4][4],
                                         uint32_t sAh, uint32_t sAl,
                                         uint32_t sBh, uint32_t sBl) {
    int lane = threadIdx.x & 31, wid = threadIdx.x >> 5;
    int wm = (wid & 1) * 32, wn = (wid >> 1) * 32;
    int rsub  = ((lane >> 3) & 1) * 8 + (lane & 7);
    int khalf = (lane >> 4) & 1;
    #pragma unroll
    for (int ks = 0; ks < 8; ks++) {
        int chunk = 2 * ks + khalf;
        uint32_t ah[2][4], al[2][4];
        #pragma unroll
        for (int mt = 0; mt < 2; mt++) {
            uint32_t o = sw_off(wm + mt * 16 + rsub, chunk);
            ldsm4(ah[mt], sAh + o);
            ldsm4(al[mt], sAl + o);
        }
        uint32_t bh[4][2], bl[4][2];
        #pragma unroll
        for (int nt2 = 0; nt2 < 2; nt2++) {
            uint32_t o = sw_off(wn + nt2 * 16 + rsub, chunk);
            uint32_t r[4];
            ldsm4(r, sBh + o);
            bh[nt2 * 2][0] = r[0]; bh[nt2 * 2 + 1][0] = r[1];
            bh[nt2 * 2][1] = r[2]; bh[nt2 * 2 + 1][1] = r[3];
            ldsm4(r, sBl + o);
            bl[nt2 * 2][0] = r[0]; bl[nt2 * 2 + 1][0] = r[1];
            bl[nt2 * 2][1] = r[2]; bl[nt2 * 2 + 1][1] = r[3];
        }
        #pragma unroll
        for (int mt = 0; mt < 2; mt++)
            #pragma unroll
            for (int nt = 0; nt < 4; nt++) {
                mma_bf16(acc[mt][nt], ah[mt], bh[nt]);
                mma_bf16(acc[mt][nt], al[mt], bh[nt]);
                mma_bf16(acc[mt][nt], ah[mt], bl[nt]);
            }
    }
}

// ---- x3 MMA, fragment-reuse for PV: 64x64 K=64 (128B rows); 4 warps 32x32
__device__ __forceinline__ void mma_pv_x3(float acc[2][4][4],
                                          uint32_t sAh, uint32_t sAl,
                                          uint32_t sBh, uint32_t sBl) {
    int lane = threadIdx.x & 31, wid = threadIdx.x >> 5;
    int wm = (wid & 1) * 32, wn = (wid >> 1) * 32;
    int rsub  = ((lane >> 3) & 1) * 8 + (lane & 7);
    int khalf = (lane >> 4) & 1;
    #pragma unroll
    for (int ks = 0; ks < 4; ks++) {
        int chunk = 2 * ks + khalf;
        uint32_t ah[2][4], al[2][4];
        #pragma unroll
        for (int mt = 0; mt < 2; mt++) {
            uint32_t o = sw_off128(wm + mt * 16 + rsub, chunk);
            ldsm4(ah[mt], sAh + o);
            ldsm4(al[mt], sAl + o);
        }
        uint32_t bh[4][2], bl[4][2];
        #pragma unroll
        for (int nt2 = 0; nt2 < 2; nt2++) {
            uint32_t o = sw_off128(wn + nt2 * 16 + rsub, chunk);
            uint32_t r[4];
            ldsm4(r, sBh + o);
            bh[nt2 * 2][0] = r[0]; bh[nt2 * 2 + 1][0] = r[1];
            bh[nt2 * 2][1] = r[2]; bh[nt2 * 2 + 1][1] = r[3];
            ldsm4(r, sBl + o);
            bl[nt2 * 2][0] = r[0]; bl[nt2 * 2 + 1][0] = r[1];
            bl[nt2 * 2][1] = r[2]; bl[nt2 * 2 + 1][1] = r[3];
        }
        #pragma unroll
        for (int mt = 0; mt < 2; mt++)
            #pragma unroll
            for (int nt = 0; nt < 4; nt++) {
                mma_bf16(acc[mt][nt], ah[mt], bh[nt]);
                mma_bf16(acc[mt][nt], al[mt], bh[nt]);
                mma_bf16(acc[mt][nt], ah[mt], bl[nt]);
            }
    }
}

// ---------------------------------------------------------------------------
// weights -> bf16 hi/lo
// ---------------------------------------------------------------------------
__global__ void convert_w_kernel(const float* __restrict__ w0, const float* __restrict__ w1,
                                 const float* __restrict__ w2, const float* __restrict__ w3,
                                 __nv_bfloat16* __restrict__ hi, __nv_bfloat16* __restrict__ lo) {
    const float* src = (blockIdx.x == 0) ? w0 : (blockIdx.x == 1) ? w1 : (blockIdx.x == 2) ? w2 : w3;
    size_t base = (size_t)blockIdx.x * EE * EE;
    for (int i = threadIdx.x; i < EE * EE; i += blockDim.x) {
        float v = src[i];
        __nv_bfloat16 h, l;
        split_bf16(v, h, l);
        hi[base + i] = h;
        lo[base + i] = l;
    }
}

// ---------------------------------------------------------------------------
// prep: adj row -> rsqrt(deg) + 512-bit mask (16 uint32 per row)
// ---------------------------------------------------------------------------
__global__ __launch_bounds__(256) void prep_kernel(const float* __restrict__ adj,
                                                   float* __restrict__ rscale,
                                                   uint32_t* __restrict__ maskbuf) {
    int row  = blockIdx.x * 8 + (threadIdx.x >> 5);
    int lane = threadIdx.x & 31;
    const float4* p = reinterpret_cast<const float4*>(adj + (size_t)row * SS) + lane * 4;
    float s = 0.f;
    uint32_t m16 = 0;
    #pragma unroll
    for (int i = 0; i < 4; i++) {
        float4 a = p[i];
        s += a.x + a.y + a.z + a.w;
        if (a.x != 0.f) m16 |= 1u << (4 * i + 0);
        if (a.y != 0.f) m16 |= 1u << (4 * i + 1);
        if (a.z != 0.f) m16 |= 1u << (4 * i + 2);
        if (a.w != 0.f) m16 |= 1u << (4 * i + 3);
    }
    float t = s;
    #pragma unroll
    for (int o = 16; o; o >>= 1) t += __shfl_xor_sync(0xffffffffu, t, o);
    if (lane == 0) rscale[row] = rsqrtf(t);
    uint32_t lo = __shfl_sync(0xffffffffu, m16, (lane & 15) * 2);
    uint32_t hi = __shfl_sync(0xffffffffu, m16, (lane & 15) * 2 + 1);
    if (lane < 16) maskbuf[(size_t)row * 16 + lane] = lo | (hi << 16);
}

// ---------------------------------------------------------------------------
// QKV MMA (fused LN; Q pre-scaled by rsqrt(deg)): grid (1536, 3), 128 thr.
// ---------------------------------------------------------------------------
__global__ __launch_bounds__(128, 2) void mm_qkv_kernel(
    const float* __restrict__ x,
    const __nv_bfloat16* __restrict__ w_hi, const __nv_bfloat16* __restrict__ w_lo,
    const float* __restrict__ bq, const float* __restrict__ bk, const float* __restrict__ bv,
    const float* __restrict__ rsp,
    __nv_bfloat16* __restrict__ qh, __nv_bfloat16* __restrict__ ql,
    __nv_bfloat16* __restrict__ kh, __nv_bfloat16* __restrict__ kl,
    __nv_bfloat16* __restrict__ vth, __nv_bfloat16* __restrict__ vtl) {
    extern __shared__ __align__(1024) char smem[];
    uint32_t sb = smem_u32(smem);
    int tid = threadIdx.x, lane = tid & 31, wid = tid >> 5;
    int y = blockIdx.y;
    int m0 = blockIdx.x * 64;
    const float* bias = (y == 0) ? bq : (y == 1) ? bk : bv;

    cp_tile256<128>(smem + MM_WH, w_hi + (size_t)y * EE * EE, EE);
    cp_tile256<128>(smem + MM_WL, w_lo + (size_t)y * EE * EE, EE);
    CP_COMMIT();
    ln_stage(x + (size_t)m0 * EE, smem + MM_AH, smem + MM_AL);  // overlaps W loads
    CP_WAIT0();
    __syncthreads();

    float acc[2][8][4];
    #pragma unroll
    for (int i = 0; i < 2; i++)
        #pragma unroll
        for (int j = 0; j < 8; j++)
            #pragma unroll
            for (int t = 0; t < 4; t++) acc[i][j][t] = 0.f;
    mma_mm_x3(acc, sb + MM_AH, sb + MM_AL, sb + MM_WH, sb + MM_WL);

    int fr = (wid & 1) * 32 + (lane >> 2);
    int fc = (wid >> 1) * 64 + ((lane & 3) << 1);

    if (y < 2) {
        __nv_bfloat16* oh = (y == 0) ? qh : kh;
        __nv_bfloat16* ol = (y == 0) ? ql : kl;
        // Q is pre-scaled by rsqrt(deg) of its row; K scale = 1
        float rsc[2][2];
        #pragma unroll
        for (int mt = 0; mt < 2; mt++)
            #pragma unroll
            for (int hh = 0; hh < 2; hh++)
                rsc[mt][hh] = (y == 0) ? rsp[m0 + fr + mt * 16 + hh * 8] : 1.0f;
        #pragma unroll
        for (int mt = 0; mt < 2; mt++) {
            #pragma unroll
            for (int nt = 0; nt < 8; nt++) {
                int c = fc + nt * 8;
                float b0 = bias[c], b1 = bias[c + 1];
                #pragma unroll
                for (int hh = 0; hh < 2; hh++) {
                    int rr = fr + mt * 16 + hh * 8;
                    float sc = rsc[mt][hh];
                    float v0 = (acc[mt][nt][hh * 2 + 0] + b0) * sc;
                    float v1 = (acc[mt][nt][hh * 2 + 1] + b1) * sc;
                    __nv_bfloat16 h0, l0, h1, l1;
                    split_bf16(v0, h0, l0); split_bf16(v1, h1, l1);
                    size_t off = (size_t)(m0 + rr) * EE + c;
                    *reinterpret_cast<uint32_t*>(oh + off) =
                        pack2(__bfloat162float(h0), __bfloat162float(h1));
                    *reinterpret_cast<uint32_t*>(ol + off) =
                        pack2(__bfloat162float(l0), __bfloat162float(l1));
                }
            }
        }
    } else {
        // stage transposed [f=128][m=64] into Ah (hi) / Al (lo) regions
        __syncthreads();     // A tile reads done
        __nv_bfloat16* sh = reinterpret_cast<__nv_bfloat16*>(smem + MM_AH);
        __nv_bfloat16* sl = reinterpret_cast<__nv_bfloat16*>(smem + MM_AL);
        #pragma unroll
        for (int mt = 0; mt < 2; mt++) {
            #pragma unroll
            for (int nt = 0; nt < 8; nt++) {
                int c = fc + nt * 8;
                float b0 = bias[c], b1 = bias[c + 1];
                #pragma unroll
                for (int hh = 0; hh < 2; hh++) {
                    int rr = fr + mt * 16 + hh * 8;
                    float v0 = acc[mt][nt][hh * 2 + 0] + b0;
                    float v1 = acc[mt][nt][hh * 2 + 1] + b1;
                    __nv_bfloat16 h, l;
                    split_bf16(v0, h, l);
                    sh[c * 64 + rr] = h; sl[c * 64 + rr] = l;
                    split_bf16(v1, h, l);
                    sh[(c + 1) * 64 + rr] = h; sl[(c + 1) * 64 + rr] = l;
                }
            }
        }
        __syncthreads();
        int b = m0 >> 9;
        int kbase = m0 & 511;
        #pragma unroll
        for (int it = 0; it < 8; it++) {
            int idx = tid + it * 128;
            int f = idx >> 3, ch = idx & 7;
            uint4 vh = *reinterpret_cast<uint4*>(sh + f * 64 + ch * 8);
            uint4 vl = *reinterpret_cast<uint4*>(sl + f * 64 + ch * 8);
            size_t off = ((size_t)b * EE + f) * SS + kbase + ch * 8;
            *reinterpret_cast<uint4*>(vth + off) = vh;
            *reinterpret_cast<uint4*>(vtl + off) = vl;
        }
    }
}

// ---------------------------------------------------------------------------
// FUSED flash attention, no-max softmax (scores bounded ~|22| << 88, so raw
// exp is overflow-safe and p/sum is exact softmax): grid (8 qt, 192 b).
// ---------------------------------------------------------------------------
__global__ __launch_bounds__(128, 2) void fused_attn_kernel(
    const __nv_bfloat16* __restrict__ qhp, const __nv_bfloat16* __restrict__ qlp,
    const __nv_bfloat16* __restrict__ khp, const __nv_bfloat16* __restrict__ klp,
    const __nv_bfloat16* __restrict__ vth, const __nv_bfloat16* __restrict__ vtl,
    const uint32_t* __restrict__ maskbuf,
    float* __restrict__ attf) {
    extern __shared__ __align__(1024) char smem[];
    uint32_t sb = smem_u32(smem);
    int tid = threadIdx.x, lane = tid & 31, wid = tid >> 5;
    int qt = blockIdx.x, b = blockIdx.y;
    size_t ar = (size_t)b * SS + qt * 64;

    float* psum = reinterpret_cast<float*>(smem + F_STAT);      // [2][64]

    cp_tile256<64>(smem + F_QH, qhp + ar * EE, EE);
    cp_tile256<64>(smem + F_QL, qlp + ar * EE, EE);
    cp_tile256<64>(smem + F_KH, khp + (size_t)b * SS * EE, EE);
    cp_tile256<64>(smem + F_KL, klp + (size_t)b * SS * EE, EE);
    cp_tile128_64(smem + F_VH, vth + (size_t)b * EE * SS, SS);
    cp_tile128_64(smem + F_VL, vtl + (size_t)b * EE * SS, SS);
    CP_COMMIT();

    int wm = (wid & 1) * 32, wns = (wid >> 1) * 32, wni = wid >> 1;
    int fr = wm + (lane >> 2);
    int fcl = (lane & 3) << 1;

    float lrow[4] = { 0.f, 0.f, 0.f, 0.f };
    float O[2][2][4][4];    // [f-half][mt][nt][e]
    #pragma unroll
    for (int h = 0; h < 2; h++)
        #pragma unroll
        for (int i = 0; i < 2; i++)
            #pragma unroll
            for (int j = 0; j < 4; j++)
                #pragma unroll
                for (int t = 0; t < 4; t++) O[h][i][j][t] = 0.f;

    const uint2* mb2 = reinterpret_cast<const uint2*>(maskbuf);

    for (int kc = 0; kc < 8; kc++) {
        CP_WAIT0();          // K(kc) + V(kc,f0) arrived
        __syncthreads();

        float S[2][4][4];
        #pragma unroll
        for (int i = 0; i < 2; i++)
            #pragma unroll
            for (int j = 0; j < 4; j++)
                #pragma unroll
                for (int t = 0; t < 4; t++) S[i][j][t] = 0.f;
        mma_s_x3(S, sb + F_QH, sb + F_QL, sb + F_KH, sb + F_KL);
        __syncthreads();     // K buffer reads done

        // per-row 64-bit masks for this chunk
        uint32_t mw[4][2];
        #pragma unroll
        for (int ri = 0; ri < 4; ri++) {
            int lr = fr + (ri >> 1) * 16 + (ri & 1) * 8;
            uint2 mv = mb2[(ar + lr) * 8 + kc];
            mw[ri][0] = mv.x; mw[ri][1] = mv.y;
        }

        // raw exp (no max subtraction) + write P (hi/lo) + partial sums
        float csum[4] = { 0.f, 0.f, 0.f, 0.f };
        #pragma unroll
        for (int mt = 0; mt < 2; mt++)
            #pragma unroll
            for (int hh = 0; hh < 2; hh++) {
                int ri = mt * 2 + hh;
                int lr = fr + mt * 16 + hh * 8;
                #pragma unroll
                for (int nt = 0; nt < 4; nt++) {
                    int c0 = wns + fcl + nt * 8;
                    uint32_t w = mw[ri][c0 >> 5];
                    int bit = c0 & 31;
                    float p0 = ((w >> bit) & 1u)       ? __expf(S[mt][nt][hh * 2 + 0]) : 0.f;
                    float p1 = ((w >> (bit + 1)) & 1u) ? __expf(S[mt][nt][hh * 2 + 1]) : 0.f;
                    csum[ri] += p0 + p1;
                    uint32_t off = sw_off128(lr, c0 >> 3) + (c0 & 7) * 2;
                    __nv_bfloat16 h0, l0, h1, l1;
                    split_bf16(p0, h0, l0); split_bf16(p1, h1, l1);
                    *reinterpret_cast<uint32_t*>(smem + F_PH + off) =
                        pack2(__bfloat162float(h0), __bfloat162float(h1));
                    *reinterpret_cast<uint32_t*>(smem + F_PL + off) =
                        pack2(__bfloat162float(l0), __bfloat162float(l1));
                }
            }
        #pragma unroll
        for (int ri = 0; ri < 4; ri++) {
            csum[ri] += __shfl_xor_sync(0xffffffffu, csum[ri], 1);
            csum[ri] += __shfl_xor_sync(0xffffffffu, csum[ri], 2);
        }
        if ((lane & 3) == 0) {
            #pragma unroll
            for (int ri = 0; ri < 4; ri++) {
                int lr = fr + (ri >> 1) * 16 + (ri & 1) * 8;
                psum[wni * 64 + lr] = csum[ri];
            }
        }
        __syncthreads();     // P + psum visible

        #pragma unroll
        for (int ri = 0; ri < 4; ri++) {
            int lr = fr + (ri >> 1) * 16 + (ri & 1) * 8;
            lrow[ri] += psum[lr] + psum[64 + lr];
        }

        // PV f-half 0 (V(kc,f0) already waited at loop top)
        mma_pv_x3(O[0], sb + F_PH, sb + F_PL, sb + F_VH, sb + F_VL);
        __syncthreads();     // V buffer free

        // prefetch V(kc,f1), then K(kc+1)
        cp_tile128_64(smem + F_VH, vth + ((size_t)b * EE + 64) * SS + kc * 64, SS);
        cp_tile128_64(smem + F_VL, vtl + ((size_t)b * EE + 64) * SS + kc * 64, SS);
        CP_COMMIT();
        if (kc < 7) {
            cp_tile256<64>(smem + F_KH, khp + ((size_t)b * SS + (kc + 1) * 64) * EE, EE);
            cp_tile256<64>(smem + F_KL, klp + ((size_t)b * SS + (kc + 1) * 64) * EE, EE);
            CP_COMMIT();
            CP_WAIT1();      // V f1 done (older group)
        } else {
            CP_WAIT0();
        }
        __syncthreads();

        // PV f-half 1
        mma_pv_x3(O[1], sb + F_PH, sb + F_PL, sb + F_VH, sb + F_VL);
        __syncthreads();     // V buffer free

        if (kc < 7) {
            cp_tile128_64(smem + F_VH, vth + (size_t)b * EE * SS + (kc + 1) * 64, SS);
            cp_tile128_64(smem + F_VL, vtl + (size_t)b * EE * SS + (kc + 1) * 64, SS);
            CP_COMMIT();
        }
    }

    // epilogue: normalize + store
    #pragma unroll
    for (int mt = 0; mt < 2; mt++)
        #pragma unroll
        for (int hh = 0; hh < 2; hh++) {
            int ri = mt * 2 + hh;
            float inv = 1.f / lrow[ri];
            size_t gm = ar + fr + mt * 16 + hh * 8;
            #pragma unroll
            for (int h = 0; h < 2; h++)
                #pragma unroll
                for (int nt = 0; nt < 4; nt++) {
                    int c = h * 64 + wns + fcl + nt * 8;
                    *reinterpret_cast<float2*>(attf + gm * EE + c) =
                        make_float2(O[h][mt][nt][hh * 2 + 0] * inv,
                                    O[h][mt][nt][hh * 2 + 1] * inv);
                }
        }
}

// ---------------------------------------------------------------------------
// out projection (fused LN): out = x + LN_ReLU(attf) @ Wo^T + bo.
// ---------------------------------------------------------------------------
__global__ __launch_bounds__(128, 2) void mm_out_kernel(
    const float* __restrict__ attf,
    const __nv_bfloat16* __restrict__ w_hi, const __nv_bfloat16* __restrict__ w_lo,
    const float* __restrict__ bo, const float* __restrict__ x,
    float* __restrict__ out) {
    extern __shared__ __align__(1024) char smem[];
    uint32_t sb = smem_u32(smem);
    int tid = threadIdx.x, lane = tid & 31, wid = tid >> 5;
    int m0 = blockIdx.x * 64;

    cp_tile256<128>(smem + MM_WH, w_hi, EE);
    cp_tile256<128>(smem + MM_WL, w_lo, EE);
    CP_COMMIT();
    ln_stage(attf + (size_t)m0 * EE, smem + MM_AH, smem + MM_AL);
    CP_WAIT0();
    __syncthreads();

    float acc[2][8][4];
    #pragma unroll
    for (int i = 0; i < 2; i++)
        #pragma unroll
        for (int j = 0; j < 8; j++)
            #pragma unroll
            for (int t = 0; t < 4; t++) acc[i][j][t] = 0.f;
    mma_mm_x3(acc, sb + MM_AH, sb + MM_AL, sb + MM_WH, sb + MM_WL);

    int fr = (wid & 1) * 32 + (lane >> 2);
    int fc = (wid >> 1) * 64 + ((lane & 3) << 1);
    #pragma unroll
    for (int mt = 0; mt < 2; mt++) {
        #pragma unroll
        for (int hh = 0; hh < 2; hh++) {
            size_t gm = (size_t)(m0 + fr + mt * 16 + hh * 8);
            #pragma unroll
            for (int nt = 0; nt < 8; nt++) {
                int c = fc + nt * 8;
                float2 xr = *reinterpret_cast<const float2*>(x + gm * EE + c);
                float v0 = acc[mt][nt][hh * 2 + 0] + bo[c] + xr.x;
                float v1 = acc[mt][nt][hh * 2 + 1] + bo[c + 1] + xr.y;
                *reinterpret_cast<float2*>(out + gm * EE + c) = make_float2(v0, v1);
            }
        }
    }
}

// ---------------------------------------------------------------------------
extern "C" void kernel_launch(void* const* d_in, const int* in_sizes, int n_in,
                              void* d_out, int out_size) {
    const float* x   = (const float*)d_in[0];
    const float* adj = (const float*)d_in[1];
    const float* Wq  = (const float*)d_in[2];
    const float* bq  = (const float*)d_in[3];
    const float* Wk  = (const float*)d_in[4];
    const float* bk  = (const float*)d_in[5];
    const float* Wv  = (const float*)d_in[6];
    const float* bv  = (const float*)d_in[7];
    const float* Wo  = (const float*)d_in[8];
    const float* bo  = (const float*)d_in[9];
    float* out = (float*)d_out;

    char* s = nullptr;
    cudaGetSymbolAddress((void**)&s, g_scratch);
    __nv_bfloat16* q_hi  = (__nv_bfloat16*)(s + O_Q_HI);
    __nv_bfloat16* q_lo  = (__nv_bfloat16*)(s + O_Q_LO);
    __nv_bfloat16* k_hi  = (__nv_bfloat16*)(s + O_K_HI);
    __nv_bfloat16* k_lo  = (__nv_bfloat16*)(s + O_K_LO);
    __nv_bfloat16* vt_hi = (__nv_bfloat16*)(s + O_VT_HI);
    __nv_bfloat16* vt_lo = (__nv_bfloat16*)(s + O_VT_LO);
    float*         attf  = (float*)(s + O_ATTO);
    __nv_bfloat16* w_hi  = (__nv_bfloat16*)(s + O_W_HI);
    __nv_bfloat16* w_lo  = (__nv_bfloat16*)(s + O_W_LO);
    float*         rs    = (float*)(s + O_RS);
    uint32_t*      mb    = (uint32_t*)(s + O_MB);

    cudaFuncSetAttribute(mm_qkv_kernel,     cudaFuncAttributeMaxDynamicSharedMemorySize, MM_SMEM);
    cudaFuncSetAttribute(fused_attn_kernel, cudaFuncAttributeMaxDynamicSharedMemorySize, F_SMEM);
    cudaFuncSetAttribute(mm_out_kernel,     cudaFuncAttributeMaxDynamicSharedMemorySize, MM_SMEM);

    convert_w_kernel<<<4, 256>>>(Wq, Wk, Wv, Wo, w_hi, w_lo);
    prep_kernel<<<NROWS / 8, 256>>>(adj, rs, mb);
    mm_qkv_kernel<<<dim3(NROWS / 64, 3), 128, MM_SMEM>>>(
        x, w_hi, w_lo, bq, bk, bv, rs,
        q_hi, q_lo, k_hi, k_lo, vt_hi, vt_lo);
    fused_attn_kernel<<<dim3(8, NB), 128, F_SMEM>>>(
        q_hi, q_lo, k_hi, k_lo, vt_hi, vt_lo, mb, attf);
    mm_out_kernel<<<NROWS / 64, 128, MM_SMEM>>>(
        attf, w_hi + 3 * EE * EE, w_lo + 3 * EE * EE, bo, x, out);
}

// round 13
// speedup vs baseline: 1.3624x; 1.3624x over previous
#include <cuda_runtime.h>
#include <cuda_fp16.h>
#include <cstdint>

#define NB 192
#define SS 512
#define EE 128
#define NROWS (NB*SS)

// ---------------- scratch (bytes) ----------------
#define B_MAT ((size_t)NROWS*EE*2)          // fp16 [NROWS,128]
#define O_Q_HI   ((size_t)0)
#define O_Q_LO   (O_Q_HI + B_MAT)
#define O_K      (O_Q_LO + B_MAT)
#define O_VT     (O_K + B_MAT)
#define O_ATTO   (O_VT + B_MAT)                       // fp32 attn out
#define O_W      (O_ATTO + (size_t)NROWS*EE*4)        // 4 weights fp16
#define O_RS     (O_W + (size_t)4*EE*EE*2)
#define O_MB     (O_RS + (size_t)NROWS*4)             // adj bitmasks, 64 B/row
#define SCRATCH_BYTES (O_MB + (size_t)NROWS*64)

__device__ __align__(1024) char g_scratch[SCRATCH_BYTES];

// ---------------- SMEM layouts ----------------
// mm kernels: Ah(16K) Al(16K) W(32K) = 64K
#define MM_AH 0
#define MM_AL 16384
#define MM_W  32768
#define MM_SMEM 65536
// fused: Qh Ql (16K ea) K (16K) Ph Pl (8K ea) V (8K) + stats
#define F_QH 0
#define F_QL 16384
#define F_K  32768
#define F_PH 49152
#define F_PL 57344
#define F_V  65536
#define F_STAT 73728
#define F_SMEM (73728 + 1024)

__device__ __forceinline__ uint32_t smem_u32(const void* p) {
    uint32_t a;
    asm("{ .reg .u64 t; cvta.to.shared.u64 t, %1; cvt.u32.u64 %0, t; }" : "=r"(a) : "l"(p));
    return a;
}

__device__ __forceinline__ uint32_t sw_off(int row, int chunk) {
    return (uint32_t)(row * 256 + ((chunk ^ (row & 7)) << 4));
}
__device__ __forceinline__ uint32_t sw_off128(int row, int chunk) {
    return (uint32_t)(row * 128 + ((chunk ^ (row & 7)) << 4));
}

#define CP_COMMIT() asm volatile("cp.async.commit_group;" ::: "memory")
#define CP_WAIT0()  asm volatile("cp.async.wait_group 0;" ::: "memory")
#define CP_WAIT1()  asm volatile("cp.async.wait_group 1;" ::: "memory")

__device__ __forceinline__ void cp16(char* dst, const void* src) {
    uint32_t d = smem_u32(dst);
    asm volatile("cp.async.cg.shared.global [%0], [%1], 16;" :: "r"(d), "l"(src));
}

template <int ROWS>
__device__ __forceinline__ void cp_tile256(char* dst, const __half* g, int pitch) {
    #pragma unroll
    for (int it = 0; it < ROWS / 8; it++) {
        int idx = threadIdx.x + it * 128;
        int row = idx >> 4, ch = idx & 15;
        cp16(dst + sw_off(row, ch), g + (size_t)row * pitch + ch * 8);
    }
}
__device__ __forceinline__ void cp_tile128_64(char* dst, const __half* g, int pitch) {
    #pragma unroll
    for (int it = 0; it < 4; it++) {
        int idx = threadIdx.x + it * 128;
        int row = idx >> 3, ch = idx & 7;
        cp16(dst + sw_off128(row, ch), g + (size_t)row * pitch + ch * 8);
    }
}

__device__ __forceinline__ void ldsm4(uint32_t* r, uint32_t a) {
    asm volatile("ldmatrix.sync.aligned.m8n8.x4.shared.b16 {%0,%1,%2,%3}, [%4];"
                 : "=r"(r[0]), "=r"(r[1]), "=r"(r[2]), "=r"(r[3]) : "r"(a));
}
__device__ __forceinline__ void mma_f16(float* c, const uint32_t* a, const uint32_t* b) {
    asm volatile(
        "mma.sync.aligned.m16n8k16.row.col.f32.f16.f16.f32 "
        "{%0,%1,%2,%3},{%4,%5,%6,%7},{%8,%9},{%0,%1,%2,%3};"
        : "+f"(c[0]), "+f"(c[1]), "+f"(c[2]), "+f"(c[3])
        : "r"(a[0]), "r"(a[1]), "r"(a[2]), "r"(a[3]), "r"(b[0]), "r"(b[1]));
}

__device__ __forceinline__ void split_half(float v, float& h, float& l) {
    __half hh = __float2half_rn(v);
    h = __half2float(hh);
    l = v - h;
}
__device__ __forceinline__ uint32_t pack2h(float a, float b) {
    __half2 t = __floats2half2_rn(a, b);
    return *reinterpret_cast<uint32_t*>(&t);
}

// ---- LN(no affine)+ReLU+split of 64 fp32 rows -> swizzled hi/lo fp16 ----
__device__ __forceinline__ void ln_stage(const float* __restrict__ src,
                                         char* dsth, char* dstl) {
    int lane = threadIdx.x & 31, wid = threadIdx.x >> 5;
    #pragma unroll
    for (int r = 0; r < 16; r++) {
        int row = wid * 16 + r;
        float4 a = reinterpret_cast<const float4*>(src + (size_t)row * EE)[lane];
        float s = a.x + a.y + a.z + a.w;
        float q = a.x * a.x + a.y * a.y + a.z * a.z + a.w * a.w;
        #pragma unroll
        for (int o = 16; o; o >>= 1) {
            s += __shfl_xor_sync(0xffffffffu, s, o);
            q += __shfl_xor_sync(0xffffffffu, q, o);
        }
        float mean = s * (1.0f / 128.0f);
        float var  = q * (1.0f / 128.0f) - mean * mean;
        float inv  = rsqrtf(var + 1e-5f);
        float r0 = fmaxf((a.x - mean) * inv, 0.f);
        float r1 = fmaxf((a.y - mean) * inv, 0.f);
        float r2 = fmaxf((a.z - mean) * inv, 0.f);
        float r3 = fmaxf((a.w - mean) * inv, 0.f);
        float h0, l0, h1, l1, h2, l2, h3, l3;
        split_half(r0, h0, l0); split_half(r1, h1, l1);
        split_half(r2, h2, l2); split_half(r3, h3, l3);
        uint2 uh, ul;
        uh.x = pack2h(h0, h1); uh.y = pack2h(h2, h3);
        ul.x = pack2h(l0, l1); ul.y = pack2h(l2, l3);
        uint32_t off = sw_off(row, lane >> 1) + (lane & 1) * 8;
        *reinterpret_cast<uint2*>(dsth + off) = uh;
        *reinterpret_cast<uint2*>(dstl + off) = ul;
    }
}

// ---- x2 MMA: A hi/lo 64-row(256B), B single 128-row(256B); 4 warps 32x64
__device__ __forceinline__ void mma_mm_x2(float acc[2][8][4],
                                          uint32_t sAh, uint32_t sAl, uint32_t sB) {
    int lane = threadIdx.x & 31, wid = threadIdx.x >> 5;
    int wm = (wid & 1) * 32, wn = (wid >> 1) * 64;
    int rsub  = ((lane >> 3) & 1) * 8 + (lane & 7);
    int khalf = (lane >> 4) & 1;
    #pragma unroll
    for (int ks = 0; ks < 8; ks++) {
        int chunk = 2 * ks + khalf;
        uint32_t ah[2][4], al[2][4];
        #pragma unroll
        for (int mt = 0; mt < 2; mt++) {
            uint32_t o = sw_off(wm + mt * 16 + rsub, chunk);
            ldsm4(ah[mt], sAh + o);
            ldsm4(al[mt], sAl + o);
        }
        uint32_t b[8][2];
        #pragma unroll
        for (int nt2 = 0; nt2 < 4; nt2++) {
            uint32_t r[4];
            ldsm4(r, sB + sw_off(wn + nt2 * 16 + rsub, chunk));
            b[nt2 * 2][0] = r[0]; b[nt2 * 2 + 1][0] = r[1];
            b[nt2 * 2][1] = r[2]; b[nt2 * 2 + 1][1] = r[3];
        }
        #pragma unroll
        for (int mt = 0; mt < 2; mt++)
            #pragma unroll
            for (int nt = 0; nt < 8; nt++) {
                mma_f16(acc[mt][nt], ah[mt], b[nt]);
                mma_f16(acc[mt][nt], al[mt], b[nt]);
            }
    }
}

// ---- x2 MMA for S: A=Q hi/lo 64-row(256B), B=K single 64-row; 4 warps 32x32
__device__ __forceinline__ void mma_s_x2(float acc[2][4][4],
                                         uint32_t sAh, uint32_t sAl, uint32_t sB) {
    int lane = threadIdx.x & 31, wid = threadIdx.x >> 5;
    int wm = (wid & 1) * 32, wn = (wid >> 1) * 32;
    int rsub  = ((lane >> 3) & 1) * 8 + (lane & 7);
    int khalf = (lane >> 4) & 1;
    #pragma unroll
    for (int ks = 0; ks < 8; ks++) {
        int chunk = 2 * ks + khalf;
        uint32_t ah[2][4], al[2][4];
        #pragma unroll
        for (int mt = 0; mt < 2; mt++) {
            uint32_t o = sw_off(wm + mt * 16 + rsub, chunk);
            ldsm4(ah[mt], sAh + o);
            ldsm4(al[mt], sAl + o);
        }
        uint32_t b[4][2];
        #pragma unroll
        for (int nt2 = 0; nt2 < 2; nt2++) {
            uint32_t r[4];
            ldsm4(r, sB + sw_off(wn + nt2 * 16 + rsub, chunk));
            b[nt2 * 2][0] = r[0]; b[nt2 * 2 + 1][0] = r[1];
            b[nt2 * 2][1] = r[2]; b[nt2 * 2 + 1][1] = r[3];
        }
        #pragma unroll
        for (int mt = 0; mt < 2; mt++)
            #pragma unroll
            for (int nt = 0; nt < 4; nt++) {
                mma_f16(acc[mt][nt], ah[mt], b[nt]);
                mma_f16(acc[mt][nt], al[mt], b[nt]);
            }
    }
}

// ---- x2 MMA for PV: A=P hi/lo, B=V single, 64-row(128B), K=64; 4 warps 32x32
__device__ __forceinline__ void mma_pv_x2(float acc[2][4][4],
                                          uint32_t sAh, uint32_t sAl, uint32_t sB) {
    int lane = threadIdx.x & 31, wid = threadIdx.x >> 5;
    int wm = (wid & 1) * 32, wn = (wid >> 1) * 32;
    int rsub  = ((lane >> 3) & 1) * 8 + (lane & 7);
    int khalf = (lane >> 4) & 1;
    #pragma unroll
    for (int ks = 0; ks < 4; ks++) {
        int chunk = 2 * ks + khalf;
        uint32_t ah[2][4], al[2][4];
        #pragma unroll
        for (int mt = 0; mt < 2; mt++) {
            uint32_t o = sw_off128(wm + mt * 16 + rsub, chunk);
            ldsm4(ah[mt], sAh + o);
            ldsm4(al[mt], sAl + o);
        }
        uint32_t b[4][2];
        #pragma unroll
        for (int nt2 = 0; nt2 < 2; nt2++) {
            uint32_t r[4];
            ldsm4(r, sB + sw_off128(wn + nt2 * 16 + rsub, chunk));
            b[nt2 * 2][0] = r[0]; b[nt2 * 2 + 1][0] = r[1];
            b[nt2 * 2][1] = r[2]; b[nt2 * 2 + 1][1] = r[3];
        }
        #pragma unroll
        for (int mt = 0; mt < 2; mt++)
            #pragma unroll
            for (int nt = 0; nt < 4; nt++) {
                mma_f16(acc[mt][nt], ah[mt], b[nt]);
                mma_f16(acc[mt][nt], al[mt], b[nt]);
            }
    }
}

// ---------------------------------------------------------------------------
// weights -> fp16
// ---------------------------------------------------------------------------
__global__ void convert_w_kernel(const float* __restrict__ w0, const float* __restrict__ w1,
                                 const float* __restrict__ w2, const float* __restrict__ w3,
                                 __half* __restrict__ wout) {
    const float* src = (blockIdx.x == 0) ? w0 : (blockIdx.x == 1) ? w1 : (blockIdx.x == 2) ? w2 : w3;
    size_t base = (size_t)blockIdx.x * EE * EE;
    for (int i = threadIdx.x; i < EE * EE; i += blockDim.x)
        wout[base + i] = __float2half_rn(src[i]);
}

// ---------------------------------------------------------------------------
// prep: adj row -> rsqrt(deg) + 512-bit mask (16 uint32 per row)
// ---------------------------------------------------------------------------
__global__ __launch_bounds__(256) void prep_kernel(const float* __restrict__ adj,
                                                   float* __restrict__ rscale,
                                                   uint32_t* __restrict__ maskbuf) {
    int row  = blockIdx.x * 8 + (threadIdx.x >> 5);
    int lane = threadIdx.x & 31;
    const float4* p = reinterpret_cast<const float4*>(adj + (size_t)row * SS) + lane * 4;
    float s = 0.f;
    uint32_t m16 = 0;
    #pragma unroll
    for (int i = 0; i < 4; i++) {
        float4 a = p[i];
        s += a.x + a.y + a.z + a.w;
        if (a.x != 0.f) m16 |= 1u << (4 * i + 0);
        if (a.y != 0.f) m16 |= 1u << (4 * i + 1);
        if (a.z != 0.f) m16 |= 1u << (4 * i + 2);
        if (a.w != 0.f) m16 |= 1u << (4 * i + 3);
    }
    float t = s;
    #pragma unroll
    for (int o = 16; o; o >>= 1) t += __shfl_xor_sync(0xffffffffu, t, o);
    if (lane == 0) rscale[row] = rsqrtf(t);
    uint32_t lo = __shfl_sync(0xffffffffu, m16, (lane & 15) * 2);
    uint32_t hi = __shfl_sync(0xffffffffu, m16, (lane & 15) * 2 + 1);
    if (lane < 16) maskbuf[(size_t)row * 16 + lane] = lo | (hi << 16);
}

// ---------------------------------------------------------------------------
// QKV MMA (fused LN; Q pre-scaled by rsqrt(deg), hi/lo; K,V single fp16)
// grid (1536, 3), 128 threads, 2 CTAs/SM.
// ---------------------------------------------------------------------------
__global__ __launch_bounds__(128, 2) void mm_qkv_kernel(
    const float* __restrict__ x,
    const __half* __restrict__ wbuf,
    const float* __restrict__ bq, const float* __restrict__ bk, const float* __restrict__ bv,
    const float* __restrict__ rsp,
    __half* __restrict__ qh, __half* __restrict__ ql,
    __half* __restrict__ kk, __half* __restrict__ vt) {
    extern __shared__ __align__(1024) char smem[];
    uint32_t sb = smem_u32(smem);
    int tid = threadIdx.x, lane = tid & 31, wid = tid >> 5;
    int y = blockIdx.y;
    int m0 = blockIdx.x * 64;
    const float* bias = (y == 0) ? bq : (y == 1) ? bk : bv;

    cp_tile256<128>(smem + MM_W, wbuf + (size_t)y * EE * EE, EE);
    CP_COMMIT();
    ln_stage(x + (size_t)m0 * EE, smem + MM_AH, smem + MM_AL);  // overlaps W loads
    CP_WAIT0();
    __syncthreads();

    float acc[2][8][4];
    #pragma unroll
    for (int i = 0; i < 2; i++)
        #pragma unroll
        for (int j = 0; j < 8; j++)
            #pragma unroll
            for (int t = 0; t < 4; t++) acc[i][j][t] = 0.f;
    mma_mm_x2(acc, sb + MM_AH, sb + MM_AL, sb + MM_W);

    int fr = (wid & 1) * 32 + (lane >> 2);
    int fc = (wid >> 1) * 64 + ((lane & 3) << 1);

    if (y == 0) {
        // Q: pre-scale by rsqrt(deg), write hi/lo fp16
        float rsc[2][2];
        #pragma unroll
        for (int mt = 0; mt < 2; mt++)
            #pragma unroll
            for (int hh = 0; hh < 2; hh++)
                rsc[mt][hh] = rsp[m0 + fr + mt * 16 + hh * 8];
        #pragma unroll
        for (int mt = 0; mt < 2; mt++) {
            #pragma unroll
            for (int nt = 0; nt < 8; nt++) {
                int c = fc + nt * 8;
                float b0 = bias[c], b1 = bias[c + 1];
                #pragma unroll
                for (int hh = 0; hh < 2; hh++) {
                    int rr = fr + mt * 16 + hh * 8;
                    float sc = rsc[mt][hh];
                    float v0 = (acc[mt][nt][hh * 2 + 0] + b0) * sc;
                    float v1 = (acc[mt][nt][hh * 2 + 1] + b1) * sc;
                    float h0, l0, h1, l1;
                    split_half(v0, h0, l0); split_half(v1, h1, l1);
                    size_t off = (size_t)(m0 + rr) * EE + c;
                    *reinterpret_cast<uint32_t*>(qh + off) = pack2h(h0, h1);
                    *reinterpret_cast<uint32_t*>(ql + off) = pack2h(l0, l1);
                }
            }
        }
    } else if (y == 1) {
        // K: single fp16
        #pragma unroll
        for (int mt = 0; mt < 2; mt++) {
            #pragma unroll
            for (int nt = 0; nt < 8; nt++) {
                int c = fc + nt * 8;
                float b0 = bias[c], b1 = bias[c + 1];
                #pragma unroll
                for (int hh = 0; hh < 2; hh++) {
                    int rr = fr + mt * 16 + hh * 8;
                    float v0 = acc[mt][nt][hh * 2 + 0] + b0;
                    float v1 = acc[mt][nt][hh * 2 + 1] + b1;
                    size_t off = (size_t)(m0 + rr) * EE + c;
                    *reinterpret_cast<uint32_t*>(kk + off) = pack2h(v0, v1);
                }
            }
        }
    } else {
        // V: stage transposed [f=128][m=64] fp16 into AH region, then write
        __syncthreads();     // A tile reads done
        __half* sh = reinterpret_cast<__half*>(smem + MM_AH);
        #pragma unroll
        for (int mt = 0; mt < 2; mt++) {
            #pragma unroll
            for (int nt = 0; nt < 8; nt++) {
                int c = fc + nt * 8;
                float b0 = bias[c], b1 = bias[c + 1];
                #pragma unroll
                for (int hh = 0; hh < 2; hh++) {
                    int rr = fr + mt * 16 + hh * 8;
                    sh[c * 64 + rr]       = __float2half_rn(acc[mt][nt][hh * 2 + 0] + b0);
                    sh[(c + 1) * 64 + rr] = __float2half_rn(acc[mt][nt][hh * 2 + 1] + b1);
                }
            }
        }
        __syncthreads();
        int b = m0 >> 9;
        int kbase = m0 & 511;
        #pragma unroll
        for (int it = 0; it < 8; it++) {
            int idx = tid + it * 128;
            int f = idx >> 3, ch = idx & 7;
            uint4 vh = *reinterpret_cast<uint4*>(sh + f * 64 + ch * 8);
            size_t off = ((size_t)b * EE + f) * SS + kbase + ch * 8;
            *reinterpret_cast<uint4*>(vt + off) = vh;
        }
    }
}

// ---------------------------------------------------------------------------
// FUSED flash attention (fp16 x2, max-subtracted online softmax):
// grid (8 qt, 192 b), 128 threads, 2 CTAs/SM.
// ---------------------------------------------------------------------------
__global__ __launch_bounds__(128, 2) void fused_attn_kernel(
    const __half* __restrict__ qhp, const __half* __restrict__ qlp,
    const __half* __restrict__ kp, const __half* __restrict__ vtp,
    const uint32_t* __restrict__ maskbuf,
    float* __restrict__ attf) {
    extern __shared__ __align__(1024) char smem[];
    uint32_t sb = smem_u32(smem);
    int tid = threadIdx.x, lane = tid & 31, wid = tid >> 5;
    int qt = blockIdx.x, b = blockIdx.y;
    size_t ar = (size_t)b * SS + qt * 64;

    float* pmax = reinterpret_cast<float*>(smem + F_STAT);      // [2][64]
    float* psum = pmax + 128;                                   // [2][64]

    cp_tile256<64>(smem + F_QH, qhp + ar * EE, EE);
    cp_tile256<64>(smem + F_QL, qlp + ar * EE, EE);
    cp_tile256<64>(smem + F_K,  kp + (size_t)b * SS * EE, EE);
    cp_tile128_64(smem + F_V,   vtp + (size_t)b * EE * SS, SS);
    CP_COMMIT();

    int wm = (wid & 1) * 32, wns = (wid >> 1) * 32, wni = wid >> 1;
    int fr = wm + (lane >> 2);
    int fcl = (lane & 3) << 1;

    float mrow[4], lrow[4];
    #pragma unroll
    for (int ri = 0; ri < 4; ri++) { mrow[ri] = -1e30f; lrow[ri] = 0.f; }
    float O[2][2][4][4];    // [f-half][mt][nt][e]
    #pragma unroll
    for (int h = 0; h < 2; h++)
        #pragma unroll
        for (int i = 0; i < 2; i++)
            #pragma unroll
            for (int j = 0; j < 4; j++)
                #pragma unroll
                for (int t = 0; t < 4; t++) O[h][i][j][t] = 0.f;

    const uint2* mb2 = reinterpret_cast<const uint2*>(maskbuf);

    for (int kc = 0; kc < 8; kc++) {
        CP_WAIT0();          // K(kc) + V(kc,f0) arrived
        __syncthreads();

        float S[2][4][4];
        #pragma unroll
        for (int i = 0; i < 2; i++)
            #pragma unroll
            for (int j = 0; j < 4; j++)
                #pragma unroll
                for (int t = 0; t < 4; t++) S[i][j][t] = 0.f;
        mma_s_x2(S, sb + F_QH, sb + F_QL, sb + F_K);
        __syncthreads();     // K buffer reads done

        // per-row 64-bit masks for this chunk
        uint32_t mw[4][2];
        #pragma unroll
        for (int ri = 0; ri < 4; ri++) {
            int lr = fr + (ri >> 1) * 16 + (ri & 1) * 8;
            uint2 mv = mb2[(ar + lr) * 8 + kc];
            mw[ri][0] = mv.x; mw[ri][1] = mv.y;
        }

        // masked per-thread max
        float cmax[4] = { -1e30f, -1e30f, -1e30f, -1e30f };
        #pragma unroll
        for (int mt = 0; mt < 2; mt++)
            #pragma unroll
            for (int hh = 0; hh < 2; hh++) {
                int ri = mt * 2 + hh;
                #pragma unroll
                for (int nt = 0; nt < 4; nt++) {
                    int c0 = wns + fcl + nt * 8;
                    uint32_t w = mw[ri][c0 >> 5];
                    int bit = c0 & 31;
                    if ((w >> bit) & 1u)       cmax[ri] = fmaxf(cmax[ri], S[mt][nt][hh * 2 + 0]);
                    if ((w >> (bit + 1)) & 1u) cmax[ri] = fmaxf(cmax[ri], S[mt][nt][hh * 2 + 1]);
                }
            }
        #pragma unroll
        for (int ri = 0; ri < 4; ri++) {
            cmax[ri] = fmaxf(cmax[ri], __shfl_xor_sync(0xffffffffu, cmax[ri], 1));
            cmax[ri] = fmaxf(cmax[ri], __shfl_xor_sync(0xffffffffu, cmax[ri], 2));
        }
        if ((lane & 3) == 0) {
            #pragma unroll
            for (int ri = 0; ri < 4; ri++) {
                int lr = fr + (ri >> 1) * 16 + (ri & 1) * 8;
                pmax[wni * 64 + lr] = cmax[ri];
            }
        }
        __syncthreads();

        float fscale[4], mn[4];
        #pragma unroll
        for (int ri = 0; ri < 4; ri++) {
            int lr = fr + (ri >> 1) * 16 + (ri & 1) * 8;
            float cm = fmaxf(pmax[lr], pmax[64 + lr]);
            mn[ri] = fmaxf(mrow[ri], cm);
            fscale[ri] = __expf(mrow[ri] - mn[ri]);
            mrow[ri] = mn[ri];
        }

        // exp + write P (fp16 hi/lo) + partial sums
        float csum[4] = { 0.f, 0.f, 0.f, 0.f };
        #pragma unroll
        for (int mt = 0; mt < 2; mt++)
            #pragma unroll
            for (int hh = 0; hh < 2; hh++) {
                int ri = mt * 2 + hh;
                int lr = fr + mt * 16 + hh * 8;
                #pragma unroll
                for (int nt = 0; nt < 4; nt++) {
                    int c0 = wns + fcl + nt * 8;
                    uint32_t w = mw[ri][c0 >> 5];
                    int bit = c0 & 31;
                    float p0 = ((w >> bit) & 1u)       ? __expf(S[mt][nt][hh * 2 + 0] - mn[ri]) : 0.f;
                    float p1 = ((w >> (bit + 1)) & 1u) ? __expf(S[mt][nt][hh * 2 + 1] - mn[ri]) : 0.f;
                    csum[ri] += p0 + p1;
                    uint32_t off = sw_off128(lr, c0 >> 3) + (c0 & 7) * 2;
                    float h0, l0, h1, l1;
                    split_half(p0, h0, l0); split_half(p1, h1, l1);
                    *reinterpret_cast<uint32_t*>(smem + F_PH + off) = pack2h(h0, h1);
                    *reinterpret_cast<uint32_t*>(smem + F_PL + off) = pack2h(l0, l1);
                }
            }
        #pragma unroll
        for (int ri = 0; ri < 4; ri++) {
            csum[ri] += __shfl_xor_sync(0xffffffffu, csum[ri], 1);
            csum[ri] += __shfl_xor_sync(0xffffffffu, csum[ri], 2);
        }
        if ((lane & 3) == 0) {
            #pragma unroll
            for (int ri = 0; ri < 4; ri++) {
                int lr = fr + (ri >> 1) * 16 + (ri & 1) * 8;
                psum[wni * 64 + lr] = csum[ri];
            }
        }
        __syncthreads();     // P + psum visible

        #pragma unroll
        for (int ri = 0; ri < 4; ri++) {
            int lr = fr + (ri >> 1) * 16 + (ri & 1) * 8;
            lrow[ri] = lrow[ri] * fscale[ri] + psum[lr] + psum[64 + lr];
        }
        #pragma unroll
        for (int mt = 0; mt < 2; mt++)
            #pragma unroll
            for (int hh = 0; hh < 2; hh++) {
                float f = fscale[mt * 2 + hh];
                #pragma unroll
                for (int h = 0; h < 2; h++)
                    #pragma unroll
                    for (int nt = 0; nt < 4; nt++) {
                        O[h][mt][nt][hh * 2 + 0] *= f;
                        O[h][mt][nt][hh * 2 + 1] *= f;
                    }
            }

        // PV f-half 0 (V(kc,f0) already waited at loop top)
        mma_pv_x2(O[0], sb + F_PH, sb + F_PL, sb + F_V);
        __syncthreads();     // V buffer free

        // prefetch V(kc,f1), then K(kc+1)
        cp_tile128_64(smem + F_V, vtp + ((size_t)b * EE + 64) * SS + kc * 64, SS);
        CP_COMMIT();
        if (kc < 7) {
            cp_tile256<64>(smem + F_K, kp + ((size_t)b * SS + (kc + 1) * 64) * EE, EE);
            CP_COMMIT();
            CP_WAIT1();      // V f1 done (older group)
        } else {
            CP_WAIT0();
        }
        __syncthreads();

        // PV f-half 1
        mma_pv_x2(O[1], sb + F_PH, sb + F_PL, sb + F_V);
        __syncthreads();     // V buffer free

        if (kc < 7) {
            cp_tile128_64(smem + F_V, vtp + (size_t)b * EE * SS + (kc + 1) * 64, SS);
            CP_COMMIT();
        }
    }

    // epilogue: normalize + store
    #pragma unroll
    for (int mt = 0; mt < 2; mt++)
        #pragma unroll
        for (int hh = 0; hh < 2; hh++) {
            int ri = mt * 2 + hh;
            float inv = 1.f / lrow[ri];
            size_t gm = ar + fr + mt * 16 + hh * 8;
            #pragma unroll
            for (int h = 0; h < 2; h++)
                #pragma unroll
                for (int nt = 0; nt < 4; nt++) {
                    int c = h * 64 + wns + fcl + nt * 8;
                    *reinterpret_cast<float2*>(attf + gm * EE + c) =
                        make_float2(O[h][mt][nt][hh * 2 + 0] * inv,
                                    O[h][mt][nt][hh * 2 + 1] * inv);
                }
        }
}

// ---------------------------------------------------------------------------
// out projection (fused LN, fp16 x2): out = x + LN_ReLU(attf) @ Wo^T + bo.
// ---------------------------------------------------------------------------
__global__ __launch_bounds__(128, 2) void mm_out_kernel(
    const float* __restrict__ attf,
    const __half* __restrict__ wo,
    const float* __restrict__ bo, const float* __restrict__ x,
    float* __restrict__ out) {
    extern __shared__ __align__(1024) char smem[];
    uint32_t sb = smem_u32(smem);
    int tid = threadIdx.x, lane = tid & 31, wid = tid >> 5;
    int m0 = blockIdx.x * 64;

    cp_tile256<128>(smem + MM_W, wo, EE);
    CP_COMMIT();
    ln_stage(attf + (size_t)m0 * EE, smem + MM_AH, smem + MM_AL);
    CP_WAIT0();
    __syncthreads();

    float acc[2][8][4];
    #pragma unroll
    for (int i = 0; i < 2; i++)
        #pragma unroll
        for (int j = 0; j < 8; j++)
            #pragma unroll
            for (int t = 0; t < 4; t++) acc[i][j][t] = 0.f;
    mma_mm_x2(acc, sb + MM_AH, sb + MM_AL, sb + MM_W);

    int fr = (wid & 1) * 32 + (lane >> 2);
    int fc = (wid >> 1) * 64 + ((lane & 3) << 1);
    #pragma unroll
    for (int mt = 0; mt < 2; mt++) {
        #pragma unroll
        for (int hh = 0; hh < 2; hh++) {
            size_t gm = (size_t)(m0 + fr + mt * 16 + hh * 8);
            #pragma unroll
            for (int nt = 0; nt < 8; nt++) {
                int c = fc + nt * 8;
                float2 xr = *reinterpret_cast<const float2*>(x + gm * EE + c);
                float v0 = acc[mt][nt][hh * 2 + 0] + bo[c] + xr.x;
                float v1 = acc[mt][nt][hh * 2 + 1] + bo[c + 1] + xr.y;
                *reinterpret_cast<float2*>(out + gm * EE + c) = make_float2(v0, v1);
            }
        }
    }
}

// ---------------------------------------------------------------------------
extern "C" void kernel_launch(void* const* d_in, const int* in_sizes, int n_in,
                              void* d_out, int out_size) {
    const float* x   = (const float*)d_in[0];
    const float* adj = (const float*)d_in[1];
    const float* Wq  = (const float*)d_in[2];
    const float* bq  = (const float*)d_in[3];
    const float* Wk  = (const float*)d_in[4];
    const float* bk  = (const float*)d_in[5];
    const float* Wv  = (const float*)d_in[6];
    const float* bv  = (const float*)d_in[7];
    const float* Wo  = (const float*)d_in[8];
    const float* bo  = (const float*)d_in[9];
    float* out = (float*)d_out;

    char* s = nullptr;
    cudaGetSymbolAddress((void**)&s, g_scratch);
    __half* q_hi = (__half*)(s + O_Q_HI);
    __half* q_lo = (__half*)(s + O_Q_LO);
    __half* kbuf = (__half*)(s + O_K);
    __half* vt   = (__half*)(s + O_VT);
    float*  attf = (float*)(s + O_ATTO);
    __half* wbuf = (__half*)(s + O_W);
    float*  rs   = (float*)(s + O_RS);
    uint32_t* mb = (uint32_t*)(s + O_MB);

    cudaFuncSetAttribute(mm_qkv_kernel,     cudaFuncAttributeMaxDynamicSharedMemorySize, MM_SMEM);
    cudaFuncSetAttribute(fused_attn_kernel, cudaFuncAttributeMaxDynamicSharedMemorySize, F_SMEM);
    cudaFuncSetAttribute(mm_out_kernel,     cudaFuncAttributeMaxDynamicSharedMemorySize, MM_SMEM);

    convert_w_kernel<<<4, 256>>>(Wq, Wk, Wv, Wo, wbuf);
    prep_kernel<<<NROWS / 8, 256>>>(adj, rs, mb);
    mm_qkv_kernel<<<dim3(NROWS / 64, 3), 128, MM_SMEM>>>(
        x, wbuf, bq, bk, bv, rs, q_hi, q_lo, kbuf, vt);
    fused_attn_kernel<<<dim3(8, NB), 128, F_SMEM>>>(
        q_hi, q_lo, kbuf, vt, mb, attf);
    mm_out_kernel<<<NROWS / 64, 128, MM_SMEM>>>(
        attf, wbuf + 3 * EE * EE, bo, x, out);
}

// round 14
// speedup vs baseline: 1.7546x; 1.2879x over previous
#include <cuda_runtime.h>
#include <cuda_fp16.h>
#include <cstdint>

#define NB 192
#define SS 512
#define EE 128
#define NROWS (NB*SS)

// ---------------- scratch (bytes) ----------------
#define B_MAT ((size_t)NROWS*EE*2)          // fp16 [NROWS,128]
#define O_Q      ((size_t)0)
#define O_K      (O_Q + B_MAT)
#define O_VT     (O_K + B_MAT)
#define O_ATTO   (O_VT + B_MAT)                       // fp32 attn out
#define O_W      (O_ATTO + (size_t)NROWS*EE*4)        // 4 weights fp16
#define O_RS     (O_W + (size_t)4*EE*EE*2)
#define O_MB     (O_RS + (size_t)NROWS*4)             // adj bitmasks, 64 B/row
#define SCRATCH_BYTES (O_MB + (size_t)NROWS*64)

__device__ __align__(1024) char g_scratch[SCRATCH_BYTES];

// ---------------- SMEM layouts ----------------
// mm kernels: A(16K) W(32K) = 48K
#define MM_A  0
#define MM_W  16384
#define MM_SMEM 49152
// fused: Q(16K) K(16K) P(8K) V(8K) + stats
#define F_Q  0
#define F_K  16384
#define F_P  32768
#define F_V  40960
#define F_STAT 49152
#define F_SMEM (49152 + 1024)

__device__ __forceinline__ uint32_t smem_u32(const void* p) {
    uint32_t a;
    asm("{ .reg .u64 t; cvta.to.shared.u64 t, %1; cvt.u32.u64 %0, t; }" : "=r"(a) : "l"(p));
    return a;
}

__device__ __forceinline__ uint32_t sw_off(int row, int chunk) {
    return (uint32_t)(row * 256 + ((chunk ^ (row & 7)) << 4));
}
__device__ __forceinline__ uint32_t sw_off128(int row, int chunk) {
    return (uint32_t)(row * 128 + ((chunk ^ (row & 7)) << 4));
}

#define CP_COMMIT() asm volatile("cp.async.commit_group;" ::: "memory")
#define CP_WAIT0()  asm volatile("cp.async.wait_group 0;" ::: "memory")
#define CP_WAIT1()  asm volatile("cp.async.wait_group 1;" ::: "memory")

__device__ __forceinline__ void cp16(char* dst, const void* src) {
    uint32_t d = smem_u32(dst);
    asm volatile("cp.async.cg.shared.global [%0], [%1], 16;" :: "r"(d), "l"(src));
}

template <int ROWS>
__device__ __forceinline__ void cp_tile256(char* dst, const __half* g, int pitch) {
    #pragma unroll
    for (int it = 0; it < ROWS / 8; it++) {
        int idx = threadIdx.x + it * 128;
        int row = idx >> 4, ch = idx & 15;
        cp16(dst + sw_off(row, ch), g + (size_t)row * pitch + ch * 8);
    }
}
__device__ __forceinline__ void cp_tile128_64(char* dst, const __half* g, int pitch) {
    #pragma unroll
    for (int it = 0; it < 4; it++) {
        int idx = threadIdx.x + it * 128;
        int row = idx >> 3, ch = idx & 7;
        cp16(dst + sw_off128(row, ch), g + (size_t)row * pitch + ch * 8);
    }
}

__device__ __forceinline__ void ldsm4(uint32_t* r, uint32_t a) {
    asm volatile("ldmatrix.sync.aligned.m8n8.x4.shared.b16 {%0,%1,%2,%3}, [%4];"
                 : "=r"(r[0]), "=r"(r[1]), "=r"(r[2]), "=r"(r[3]) : "r"(a));
}
__device__ __forceinline__ void mma_f16(float* c, const uint32_t* a, const uint32_t* b) {
    asm volatile(
        "mma.sync.aligned.m16n8k16.row.col.f32.f16.f16.f32 "
        "{%0,%1,%2,%3},{%4,%5,%6,%7},{%8,%9},{%0,%1,%2,%3};"
        : "+f"(c[0]), "+f"(c[1]), "+f"(c[2]), "+f"(c[3])
        : "r"(a[0]), "r"(a[1]), "r"(a[2]), "r"(a[3]), "r"(b[0]), "r"(b[1]));
}

__device__ __forceinline__ uint32_t pack2h(float a, float b) {
    __half2 t = __floats2half2_rn(a, b);
    return *reinterpret_cast<uint32_t*>(&t);
}

// ---- LN(no affine)+ReLU of 64 fp32 rows -> swizzled fp16 tile ----
__device__ __forceinline__ void ln_stage(const float* __restrict__ src, char* dst) {
    int lane = threadIdx.x & 31, wid = threadIdx.x >> 5;
    #pragma unroll
    for (int r = 0; r < 16; r++) {
        int row = wid * 16 + r;
        float4 a = reinterpret_cast<const float4*>(src + (size_t)row * EE)[lane];
        float s = a.x + a.y + a.z + a.w;
        float q = a.x * a.x + a.y * a.y + a.z * a.z + a.w * a.w;
        #pragma unroll
        for (int o = 16; o; o >>= 1) {
            s += __shfl_xor_sync(0xffffffffu, s, o);
            q += __shfl_xor_sync(0xffffffffu, q, o);
        }
        float mean = s * (1.0f / 128.0f);
        float var  = q * (1.0f / 128.0f) - mean * mean;
        float inv  = rsqrtf(var + 1e-5f);
        float r0 = fmaxf((a.x - mean) * inv, 0.f);
        float r1 = fmaxf((a.y - mean) * inv, 0.f);
        float r2 = fmaxf((a.z - mean) * inv, 0.f);
        float r3 = fmaxf((a.w - mean) * inv, 0.f);
        uint2 uh;
        uh.x = pack2h(r0, r1); uh.y = pack2h(r2, r3);
        uint32_t off = sw_off(row, lane >> 1) + (lane & 1) * 8;
        *reinterpret_cast<uint2*>(dst + off) = uh;
    }
}

// ---- x1 MMA: A 64-row(256B), B 128-row(256B); 4 warps 32x64
__device__ __forceinline__ void mma_mm_x1(float acc[2][8][4],
                                          uint32_t sA, uint32_t sB) {
    int lane = threadIdx.x & 31, wid = threadIdx.x >> 5;
    int wm = (wid & 1) * 32, wn = (wid >> 1) * 64;
    int rsub  = ((lane >> 3) & 1) * 8 + (lane & 7);
    int khalf = (lane >> 4) & 1;
    #pragma unroll
    for (int ks = 0; ks < 8; ks++) {
        int chunk = 2 * ks + khalf;
        uint32_t a[2][4];
        #pragma unroll
        for (int mt = 0; mt < 2; mt++)
            ldsm4(a[mt], sA + sw_off(wm + mt * 16 + rsub, chunk));
        uint32_t b[8][2];
        #pragma unroll
        for (int nt2 = 0; nt2 < 4; nt2++) {
            uint32_t r[4];
            ldsm4(r, sB + sw_off(wn + nt2 * 16 + rsub, chunk));
            b[nt2 * 2][0] = r[0]; b[nt2 * 2 + 1][0] = r[1];
            b[nt2 * 2][1] = r[2]; b[nt2 * 2 + 1][1] = r[3];
        }
        #pragma unroll
        for (int mt = 0; mt < 2; mt++)
            #pragma unroll
            for (int nt = 0; nt < 8; nt++)
                mma_f16(acc[mt][nt], a[mt], b[nt]);
    }
}

// ---- x1 MMA for S: A=Q 64-row(256B), B=K 64-row; 4 warps 32x32
__device__ __forceinline__ void mma_s_x1(float acc[2][4][4],
                                         uint32_t sA, uint32_t sB) {
    int lane = threadIdx.x & 31, wid = threadIdx.x >> 5;
    int wm = (wid & 1) * 32, wn = (wid >> 1) * 32;
    int rsub  = ((lane >> 3) & 1) * 8 + (lane & 7);
    int khalf = (lane >> 4) & 1;
    #pragma unroll
    for (int ks = 0; ks < 8; ks++) {
        int chunk = 2 * ks + khalf;
        uint32_t a[2][4];
        #pragma unroll
        for (int mt = 0; mt < 2; mt++)
            ldsm4(a[mt], sA + sw_off(wm + mt * 16 + rsub, chunk));
        uint32_t b[4][2];
        #pragma unroll
        for (int nt2 = 0; nt2 < 2; nt2++) {
            uint32_t r[4];
            ldsm4(r, sB + sw_off(wn + nt2 * 16 + rsub, chunk));
            b[nt2 * 2][0] = r[0]; b[nt2 * 2 + 1][0] = r[1];
            b[nt2 * 2][1] = r[2]; b[nt2 * 2 + 1][1] = r[3];
        }
        #pragma unroll
        for (int mt = 0; mt < 2; mt++)
            #pragma unroll
            for (int nt = 0; nt < 4; nt++)
                mma_f16(acc[mt][nt], a[mt], b[nt]);
    }
}

// ---- x1 MMA for PV: A=P, B=V, 64-row(128B), K=64; 4 warps 32x32
__device__ __forceinline__ void mma_pv_x1(float acc[2][4][4],
                                          uint32_t sA, uint32_t sB) {
    int lane = threadIdx.x & 31, wid = threadIdx.x >> 5;
    int wm = (wid & 1) * 32, wn = (wid >> 1) * 32;
    int rsub  = ((lane >> 3) & 1) * 8 + (lane & 7);
    int khalf = (lane >> 4) & 1;
    #pragma unroll
    for (int ks = 0; ks < 4; ks++) {
        int chunk = 2 * ks + khalf;
        uint32_t a[2][4];
        #pragma unroll
        for (int mt = 0; mt < 2; mt++)
            ldsm4(a[mt], sA + sw_off128(wm + mt * 16 + rsub, chunk));
        uint32_t b[4][2];
        #pragma unroll
        for (int nt2 = 0; nt2 < 2; nt2++) {
            uint32_t r[4];
            ldsm4(r, sB + sw_off128(wn + nt2 * 16 + rsub, chunk));
            b[nt2 * 2][0] = r[0]; b[nt2 * 2 + 1][0] = r[1];
            b[nt2 * 2][1] = r[2]; b[nt2 * 2 + 1][1] = r[3];
        }
        #pragma unroll
        for (int mt = 0; mt < 2; mt++)
            #pragma unroll
            for (int nt = 0; nt < 4; nt++)
                mma_f16(acc[mt][nt], a[mt], b[nt]);
    }
}

// ---------------------------------------------------------------------------
// weights -> fp16
// ---------------------------------------------------------------------------
__global__ void convert_w_kernel(const float* __restrict__ w0, const float* __restrict__ w1,
                                 const float* __restrict__ w2, const float* __restrict__ w3,
                                 __half* __restrict__ wout) {
    const float* src = (blockIdx.x == 0) ? w0 : (blockIdx.x == 1) ? w1 : (blockIdx.x == 2) ? w2 : w3;
    size_t base = (size_t)blockIdx.x * EE * EE;
    for (int i = threadIdx.x; i < EE * EE; i += blockDim.x)
        wout[base + i] = __float2half_rn(src[i]);
}

// ---------------------------------------------------------------------------
// prep: adj row -> rsqrt(deg) + 512-bit mask (16 uint32 per row)
// ---------------------------------------------------------------------------
__global__ __launch_bounds__(256) void prep_kernel(const float* __restrict__ adj,
                                                   float* __restrict__ rscale,
                                                   uint32_t* __restrict__ maskbuf) {
    int row  = blockIdx.x * 8 + (threadIdx.x >> 5);
    int lane = threadIdx.x & 31;
    const float4* p = reinterpret_cast<const float4*>(adj + (size_t)row * SS) + lane * 4;
    float s = 0.f;
    uint32_t m16 = 0;
    #pragma unroll
    for (int i = 0; i < 4; i++) {
        float4 a = p[i];
        s += a.x + a.y + a.z + a.w;
        if (a.x != 0.f) m16 |= 1u << (4 * i + 0);
        if (a.y != 0.f) m16 |= 1u << (4 * i + 1);
        if (a.z != 0.f) m16 |= 1u << (4 * i + 2);
        if (a.w != 0.f) m16 |= 1u << (4 * i + 3);
    }
    float t = s;
    #pragma unroll
    for (int o = 16; o; o >>= 1) t += __shfl_xor_sync(0xffffffffu, t, o);
    if (lane == 0) rscale[row] = rsqrtf(t);
    uint32_t lo = __shfl_sync(0xffffffffu, m16, (lane & 15) * 2);
    uint32_t hi = __shfl_sync(0xffffffffu, m16, (lane & 15) * 2 + 1);
    if (lane < 16) maskbuf[(size_t)row * 16 + lane] = lo | (hi << 16);
}

// ---------------------------------------------------------------------------
// QKV MMA (fused LN; Q pre-scaled by rsqrt(deg)): grid (1536, 3), 128 thr.
// ---------------------------------------------------------------------------
__global__ __launch_bounds__(128, 2) void mm_qkv_kernel(
    const float* __restrict__ x,
    const __half* __restrict__ wbuf,
    const float* __restrict__ bq, const float* __restrict__ bk, const float* __restrict__ bv,
    const float* __restrict__ rsp,
    __half* __restrict__ qq, __half* __restrict__ kk, __half* __restrict__ vt) {
    extern __shared__ __align__(1024) char smem[];
    uint32_t sb = smem_u32(smem);
    int tid = threadIdx.x, lane = tid & 31, wid = tid >> 5;
    int y = blockIdx.y;
    int m0 = blockIdx.x * 64;
    const float* bias = (y == 0) ? bq : (y == 1) ? bk : bv;

    cp_tile256<128>(smem + MM_W, wbuf + (size_t)y * EE * EE, EE);
    CP_COMMIT();
    ln_stage(x + (size_t)m0 * EE, smem + MM_A);  // overlaps W loads
    CP_WAIT0();
    __syncthreads();

    float acc[2][8][4];
    #pragma unroll
    for (int i = 0; i < 2; i++)
        #pragma unroll
        for (int j = 0; j < 8; j++)
            #pragma unroll
            for (int t = 0; t < 4; t++) acc[i][j][t] = 0.f;
    mma_mm_x1(acc, sb + MM_A, sb + MM_W);

    int fr = (wid & 1) * 32 + (lane >> 2);
    int fc = (wid >> 1) * 64 + ((lane & 3) << 1);

    if (y < 2) {
        __half* ob = (y == 0) ? qq : kk;
        float rsc[2][2];
        #pragma unroll
        for (int mt = 0; mt < 2; mt++)
            #pragma unroll
            for (int hh = 0; hh < 2; hh++)
                rsc[mt][hh] = (y == 0) ? rsp[m0 + fr + mt * 16 + hh * 8] : 1.0f;
        #pragma unroll
        for (int mt = 0; mt < 2; mt++) {
            #pragma unroll
            for (int nt = 0; nt < 8; nt++) {
                int c = fc + nt * 8;
                float b0 = bias[c], b1 = bias[c + 1];
                #pragma unroll
                for (int hh = 0; hh < 2; hh++) {
                    int rr = fr + mt * 16 + hh * 8;
                    float sc = rsc[mt][hh];
                    float v0 = (acc[mt][nt][hh * 2 + 0] + b0) * sc;
                    float v1 = (acc[mt][nt][hh * 2 + 1] + b1) * sc;
                    size_t off = (size_t)(m0 + rr) * EE + c;
                    *reinterpret_cast<uint32_t*>(ob + off) = pack2h(v0, v1);
                }
            }
        }
    } else {
        // V: stage transposed [f=128][m=64] fp16, then coalesced write
        __syncthreads();     // A tile reads done
        __half* sh = reinterpret_cast<__half*>(smem + MM_A);
        #pragma unroll
        for (int mt = 0; mt < 2; mt++) {
            #pragma unroll
            for (int nt = 0; nt < 8; nt++) {
                int c = fc + nt * 8;
                float b0 = bias[c], b1 = bias[c + 1];
                #pragma unroll
                for (int hh = 0; hh < 2; hh++) {
                    int rr = fr + mt * 16 + hh * 8;
                    sh[c * 64 + rr]       = __float2half_rn(acc[mt][nt][hh * 2 + 0] + b0);
                    sh[(c + 1) * 64 + rr] = __float2half_rn(acc[mt][nt][hh * 2 + 1] + b1);
                }
            }
        }
        __syncthreads();
        int b = m0 >> 9;
        int kbase = m0 & 511;
        #pragma unroll
        for (int it = 0; it < 8; it++) {
            int idx = tid + it * 128;
            int f = idx >> 3, ch = idx & 7;
            uint4 vh = *reinterpret_cast<uint4*>(sh + f * 64 + ch * 8);
            size_t off = ((size_t)b * EE + f) * SS + kbase + ch * 8;
            *reinterpret_cast<uint4*>(vt + off) = vh;
        }
    }
}

// ---------------------------------------------------------------------------
// FUSED flash attention (fp16 x1, max-subtracted online softmax):
// grid (8 qt, 192 b), 128 threads.
// ---------------------------------------------------------------------------
__global__ __launch_bounds__(128, 2) void fused_attn_kernel(
    const __half* __restrict__ qp, const __half* __restrict__ kp,
    const __half* __restrict__ vtp,
    const uint32_t* __restrict__ maskbuf,
    float* __restrict__ attf) {
    extern __shared__ __align__(1024) char smem[];
    uint32_t sb = smem_u32(smem);
    int tid = threadIdx.x, lane = tid & 31, wid = tid >> 5;
    int qt = blockIdx.x, b = blockIdx.y;
    size_t ar = (size_t)b * SS + qt * 64;

    float* pmax = reinterpret_cast<float*>(smem + F_STAT);      // [2][64]
    float* psum = pmax + 128;                                   // [2][64]

    cp_tile256<64>(smem + F_Q, qp + ar * EE, EE);
    cp_tile256<64>(smem + F_K, kp + (size_t)b * SS * EE, EE);
    cp_tile128_64(smem + F_V,  vtp + (size_t)b * EE * SS, SS);
    CP_COMMIT();

    int wm = (wid & 1) * 32, wns = (wid >> 1) * 32, wni = wid >> 1;
    int fr = wm + (lane >> 2);
    int fcl = (lane & 3) << 1;

    float mrow[4], lrow[4];
    #pragma unroll
    for (int ri = 0; ri < 4; ri++) { mrow[ri] = -1e30f; lrow[ri] = 0.f; }
    float O[2][2][4][4];    // [f-half][mt][nt][e]
    #pragma unroll
    for (int h = 0; h < 2; h++)
        #pragma unroll
        for (int i = 0; i < 2; i++)
            #pragma unroll
            for (int j = 0; j < 4; j++)
                #pragma unroll
                for (int t = 0; t < 4; t++) O[h][i][j][t] = 0.f;

    const uint2* mb2 = reinterpret_cast<const uint2*>(maskbuf);

    for (int kc = 0; kc < 8; kc++) {
        CP_WAIT0();          // K(kc) + V(kc,f0) arrived
        __syncthreads();

        float S[2][4][4];
        #pragma unroll
        for (int i = 0; i < 2; i++)
            #pragma unroll
            for (int j = 0; j < 4; j++)
                #pragma unroll
                for (int t = 0; t < 4; t++) S[i][j][t] = 0.f;
        mma_s_x1(S, sb + F_Q, sb + F_K);
        __syncthreads();     // K buffer reads done

        uint32_t mw[4][2];
        #pragma unroll
        for (int ri = 0; ri < 4; ri++) {
            int lr = fr + (ri >> 1) * 16 + (ri & 1) * 8;
            uint2 mv = mb2[(ar + lr) * 8 + kc];
            mw[ri][0] = mv.x; mw[ri][1] = mv.y;
        }

        // masked per-thread max
        float cmax[4] = { -1e30f, -1e30f, -1e30f, -1e30f };
        #pragma unroll
        for (int mt = 0; mt < 2; mt++)
            #pragma unroll
            for (int hh = 0; hh < 2; hh++) {
                int ri = mt * 2 + hh;
                #pragma unroll
                for (int nt = 0; nt < 4; nt++) {
                    int c0 = wns + fcl + nt * 8;
                    uint32_t w = mw[ri][c0 >> 5];
                    int bit = c0 & 31;
                    if ((w >> bit) & 1u)       cmax[ri] = fmaxf(cmax[ri], S[mt][nt][hh * 2 + 0]);
                    if ((w >> (bit + 1)) & 1u) cmax[ri] = fmaxf(cmax[ri], S[mt][nt][hh * 2 + 1]);
                }
            }
        #pragma unroll
        for (int ri = 0; ri < 4; ri++) {
            cmax[ri] = fmaxf(cmax[ri], __shfl_xor_sync(0xffffffffu, cmax[ri], 1));
            cmax[ri] = fmaxf(cmax[ri], __shfl_xor_sync(0xffffffffu, cmax[ri], 2));
        }
        if ((lane & 3) == 0) {
            #pragma unroll
            for (int ri = 0; ri < 4; ri++) {
                int lr = fr + (ri >> 1) * 16 + (ri & 1) * 8;
                pmax[wni * 64 + lr] = cmax[ri];
            }
        }
        __syncthreads();

        float fscale[4], mn[4];
        #pragma unroll
        for (int ri = 0; ri < 4; ri++) {
            int lr = fr + (ri >> 1) * 16 + (ri & 1) * 8;
            float cm = fmaxf(pmax[lr], pmax[64 + lr]);
            mn[ri] = fmaxf(mrow[ri], cm);
            fscale[ri] = __expf(mrow[ri] - mn[ri]);
            mrow[ri] = mn[ri];
        }

        // exp + write P (fp16) + partial sums
        float csum[4] = { 0.f, 0.f, 0.f, 0.f };
        #pragma unroll
        for (int mt = 0; mt < 2; mt++)
            #pragma unroll
            for (int hh = 0; hh < 2; hh++) {
                int ri = mt * 2 + hh;
                int lr = fr + mt * 16 + hh * 8;
                #pragma unroll
                for (int nt = 0; nt < 4; nt++) {
                    int c0 = wns + fcl + nt * 8;
                    uint32_t w = mw[ri][c0 >> 5];
                    int bit = c0 & 31;
                    float p0 = ((w >> bit) & 1u)       ? __expf(S[mt][nt][hh * 2 + 0] - mn[ri]) : 0.f;
                    float p1 = ((w >> (bit + 1)) & 1u) ? __expf(S[mt][nt][hh * 2 + 1] - mn[ri]) : 0.f;
                    csum[ri] += p0 + p1;
                    uint32_t off = sw_off128(lr, c0 >> 3) + (c0 & 7) * 2;
                    *reinterpret_cast<uint32_t*>(smem + F_P + off) = pack2h(p0, p1);
                }
            }
        #pragma unroll
        for (int ri = 0; ri < 4; ri++) {
            csum[ri] += __shfl_xor_sync(0xffffffffu, csum[ri], 1);
            csum[ri] += __shfl_xor_sync(0xffffffffu, csum[ri], 2);
        }
        if ((lane & 3) == 0) {
            #pragma unroll
            for (int ri = 0; ri < 4; ri++) {
                int lr = fr + (ri >> 1) * 16 + (ri & 1) * 8;
                psum[wni * 64 + lr] = csum[ri];
            }
        }
        __syncthreads();     // P + psum visible

        #pragma unroll
        for (int ri = 0; ri < 4; ri++) {
            int lr = fr + (ri >> 1) * 16 + (ri & 1) * 8;
            lrow[ri] = lrow[ri] * fscale[ri] + psum[lr] + psum[64 + lr];
        }
        #pragma unroll
        for (int mt = 0; mt < 2; mt++)
            #pragma unroll
            for (int hh = 0; hh < 2; hh++) {
                float f = fscale[mt * 2 + hh];
                #pragma unroll
                for (int h = 0; h < 2; h++)
                    #pragma unroll
                    for (int nt = 0; nt < 4; nt++) {
                        O[h][mt][nt][hh * 2 + 0] *= f;
                        O[h][mt][nt][hh * 2 + 1] *= f;
                    }
            }

        // PV f-half 0 (V(kc,f0) already waited at loop top)
        mma_pv_x1(O[0], sb + F_P, sb + F_V);
        __syncthreads();     // V buffer free

        // prefetch V(kc,f1), then K(kc+1)
        cp_tile128_64(smem + F_V, vtp + ((size_t)b * EE + 64) * SS + kc * 64, SS);
        CP_COMMIT();
        if (kc < 7) {
            cp_tile256<64>(smem + F_K, kp + ((size_t)b * SS + (kc + 1) * 64) * EE, EE);
            CP_COMMIT();
            CP_WAIT1();      // V f1 done (older group)
        } else {
            CP_WAIT0();
        }
        __syncthreads();

        // PV f-half 1
        mma_pv_x1(O[1], sb + F_P, sb + F_V);
        __syncthreads();     // V buffer free

        if (kc < 7) {
            cp_tile128_64(smem + F_V, vtp + (size_t)b * EE * SS + (kc + 1) * 64, SS);
            CP_COMMIT();
        }
    }

    // epilogue: normalize + store
    #pragma unroll
    for (int mt = 0; mt < 2; mt++)
        #pragma unroll
        for (int hh = 0; hh < 2; hh++) {
            int ri = mt * 2 + hh;
            float inv = 1.f / lrow[ri];
            size_t gm = ar + fr + mt * 16 + hh * 8;
            #pragma unroll
            for (int h = 0; h < 2; h++)
                #pragma unroll
                for (int nt = 0; nt < 4; nt++) {
                    int c = h * 64 + wns + fcl + nt * 8;
                    *reinterpret_cast<float2*>(attf + gm * EE + c) =
                        make_float2(O[h][mt][nt][hh * 2 + 0] * inv,
                                    O[h][mt][nt][hh * 2 + 1] * inv);
                }
        }
}

// ---------------------------------------------------------------------------
// out projection (fused LN, fp16 x1): out = x + LN_ReLU(attf) @ Wo^T + bo.
// ---------------------------------------------------------------------------
__global__ __launch_bounds__(128, 2) void mm_out_kernel(
    const float* __restrict__ attf,
    const __half* __restrict__ wo,
    const float* __restrict__ bo, const float* __restrict__ x,
    float* __restrict__ out) {
    extern __shared__ __align__(1024) char smem[];
    uint32_t sb = smem_u32(smem);
    int tid = threadIdx.x, lane = tid & 31, wid = tid >> 5;
    int m0 = blockIdx.x * 64;

    cp_tile256<128>(smem + MM_W, wo, EE);
    CP_COMMIT();
    ln_stage(attf + (size_t)m0 * EE, smem + MM_A);
    CP_WAIT0();
    __syncthreads();

    float acc[2][8][4];
    #pragma unroll
    for (int i = 0; i < 2; i++)
        #pragma unroll
        for (int j = 0; j < 8; j++)
            #pragma unroll
            for (int t = 0; t < 4; t++) acc[i][j][t] = 0.f;
    mma_mm_x1(acc, sb + MM_A, sb + MM_W);

    int fr = (wid & 1) * 32 + (lane >> 2);
    int fc = (wid >> 1) * 64 + ((lane & 3) << 1);
    #pragma unroll
    for (int mt = 0; mt < 2; mt++) {
        #pragma unroll
        for (int hh = 0; hh < 2; hh++) {
            size_t gm = (size_t)(m0 + fr + mt * 16 + hh * 8);
            #pragma unroll
            for (int nt = 0; nt < 8; nt++) {
                int c = fc + nt * 8;
                float2 xr = *reinterpret_cast<const float2*>(x + gm * EE + c);
                float v0 = acc[mt][nt][hh * 2 + 0] + bo[c] + xr.x;
                float v1 = acc[mt][nt][hh * 2 + 1] + bo[c + 1] + xr.y;
                *reinterpret_cast<float2*>(out + gm * EE + c) = make_float2(v0, v1);
            }
        }
    }
}

// ---------------------------------------------------------------------------
extern "C" void kernel_launch(void* const* d_in, const int* in_sizes, int n_in,
                              void* d_out, int out_size) {
    const float* x   = (const float*)d_in[0];
    const float* adj = (const float*)d_in[1];
    const float* Wq  = (const float*)d_in[2];
    const float* bq  = (const float*)d_in[3];
    const float* Wk  = (const float*)d_in[4];
    const float* bk  = (const float*)d_in[5];
    const float* Wv  = (const float*)d_in[6];
    const float* bv  = (const float*)d_in[7];
    const float* Wo  = (const float*)d_in[8];
    const float* bo  = (const float*)d_in[9];
    float* out = (float*)d_out;

    char* s = nullptr;
    cudaGetSymbolAddress((void**)&s, g_scratch);
    __half* qbuf = (__half*)(s + O_Q);
    __half* kbuf = (__half*)(s + O_K);
    __half* vt   = (__half*)(s + O_VT);
    float*  attf = (float*)(s + O_ATTO);
    __half* wbuf = (__half*)(s + O_W);
    float*  rs   = (float*)(s + O_RS);
    uint32_t* mb = (uint32_t*)(s + O_MB);

    cudaFuncSetAttribute(mm_qkv_kernel,     cudaFuncAttributeMaxDynamicSharedMemorySize, MM_SMEM);
    cudaFuncSetAttribute(fused_attn_kernel, cudaFuncAttributeMaxDynamicSharedMemorySize, F_SMEM);
    cudaFuncSetAttribute(mm_out_kernel,     cudaFuncAttributeMaxDynamicSharedMemorySize, MM_SMEM);

    convert_w_kernel<<<4, 256>>>(Wq, Wk, Wv, Wo, wbuf);
    prep_kernel<<<NROWS / 8, 256>>>(adj, rs, mb);
    mm_qkv_kernel<<<dim3(NROWS / 64, 3), 128, MM_SMEM>>>(
        x, wbuf, bq, bk, bv, rs, qbuf, kbuf, vt);
    fused_attn_kernel<<<dim3(8, NB), 128, F_SMEM>>>(
        qbuf, kbuf, vt, mb, attf);
    mm_out_kernel<<<NROWS / 64, 128, MM_SMEM>>>(
        attf, wbuf + 3 * EE * EE, bo, x, out);
}

// round 15
// speedup vs baseline: 1.9324x; 1.1014x over previous
#include <cuda_runtime.h>
#include <cuda_fp16.h>
#include <cstdint>

#define NB 192
#define SS 512
#define EE 128
#define NROWS (NB*SS)

// ---------------- scratch (bytes) ----------------
#define B_MAT ((size_t)NROWS*EE*2)          // fp16 [NROWS,128]
#define O_Q      ((size_t)0)
#define O_K      (O_Q + B_MAT)
#define O_VT     (O_K + B_MAT)
#define O_ATTO   (O_VT + B_MAT)                       // fp32 attn out
#define O_W      (O_ATTO + (size_t)NROWS*EE*4)        // 4 weights fp16
#define O_RS     (O_W + (size_t)4*EE*EE*2)
#define O_MB     (O_RS + (size_t)NROWS*4)             // adj bitmasks, 64 B/row
#define SCRATCH_BYTES (O_MB + (size_t)NROWS*64)

__device__ __align__(1024) char g_scratch[SCRATCH_BYTES];

// ---------------- SMEM layouts ----------------
// mm kernels: A(16K) W(32K) = 48K
#define MM_A  0
#define MM_W  16384
#define MM_SMEM 49152
// fused: Q(16K) K(16K) P(8K) V(16K, both f-halves) + stats
#define F_Q  0
#define F_K  16384
#define F_P  32768
#define F_V  40960
#define F_STAT 57344
#define F_SMEM (57344 + 1024)

__device__ __forceinline__ uint32_t smem_u32(const void* p) {
    uint32_t a;
    asm("{ .reg .u64 t; cvta.to.shared.u64 t, %1; cvt.u32.u64 %0, t; }" : "=r"(a) : "l"(p));
    return a;
}

__device__ __forceinline__ uint32_t sw_off(int row, int chunk) {
    return (uint32_t)(row * 256 + ((chunk ^ (row & 7)) << 4));
}
__device__ __forceinline__ uint32_t sw_off128(int row, int chunk) {
    return (uint32_t)(row * 128 + ((chunk ^ (row & 7)) << 4));
}

#define CP_COMMIT() asm volatile("cp.async.commit_group;" ::: "memory")
#define CP_WAIT0()  asm volatile("cp.async.wait_group 0;" ::: "memory")

__device__ __forceinline__ void cp16(char* dst, const void* src) {
    uint32_t d = smem_u32(dst);
    asm volatile("cp.async.cg.shared.global [%0], [%1], 16;" :: "r"(d), "l"(src));
}

template <int ROWS>
__device__ __forceinline__ void cp_tile256(char* dst, const __half* g, int pitch) {
    #pragma unroll
    for (int it = 0; it < ROWS / 8; it++) {
        int idx = threadIdx.x + it * 128;
        int row = idx >> 4, ch = idx & 15;
        cp16(dst + sw_off(row, ch), g + (size_t)row * pitch + ch * 8);
    }
}
template <int ROWS>
__device__ __forceinline__ void cp_tile128(char* dst, const __half* g, int pitch) {
    #pragma unroll
    for (int it = 0; it < ROWS / 16; it++) {
        int idx = threadIdx.x + it * 128;
        int row = idx >> 3, ch = idx & 7;
        cp16(dst + sw_off128(row, ch), g + (size_t)row * pitch + ch * 8);
    }
}

__device__ __forceinline__ void ldsm4(uint32_t* r, uint32_t a) {
    asm volatile("ldmatrix.sync.aligned.m8n8.x4.shared.b16 {%0,%1,%2,%3}, [%4];"
                 : "=r"(r[0]), "=r"(r[1]), "=r"(r[2]), "=r"(r[3]) : "r"(a));
}
__device__ __forceinline__ void mma_f16(float* c, const uint32_t* a, const uint32_t* b) {
    asm volatile(
        "mma.sync.aligned.m16n8k16.row.col.f32.f16.f16.f32 "
        "{%0,%1,%2,%3},{%4,%5,%6,%7},{%8,%9},{%0,%1,%2,%3};"
        : "+f"(c[0]), "+f"(c[1]), "+f"(c[2]), "+f"(c[3])
        : "r"(a[0]), "r"(a[1]), "r"(a[2]), "r"(a[3]), "r"(b[0]), "r"(b[1]));
}

__device__ __forceinline__ uint32_t pack2h(float a, float b) {
    __half2 t = __floats2half2_rn(a, b);
    return *reinterpret_cast<uint32_t*>(&t);
}

// ---- LN(no affine)+ReLU of 64 fp32 rows -> swizzled fp16 tile ----
__device__ __forceinline__ void ln_stage(const float* __restrict__ src, char* dst) {
    int lane = threadIdx.x & 31, wid = threadIdx.x >> 5;
    #pragma unroll
    for (int r = 0; r < 16; r++) {
        int row = wid * 16 + r;
        float4 a = reinterpret_cast<const float4*>(src + (size_t)row * EE)[lane];
        float s = a.x + a.y + a.z + a.w;
        float q = a.x * a.x + a.y * a.y + a.z * a.z + a.w * a.w;
        #pragma unroll
        for (int o = 16; o; o >>= 1) {
            s += __shfl_xor_sync(0xffffffffu, s, o);
            q += __shfl_xor_sync(0xffffffffu, q, o);
        }
        float mean = s * (1.0f / 128.0f);
        float var  = q * (1.0f / 128.0f) - mean * mean;
        float inv  = rsqrtf(var + 1e-5f);
        float r0 = fmaxf((a.x - mean) * inv, 0.f);
        float r1 = fmaxf((a.y - mean) * inv, 0.f);
        float r2 = fmaxf((a.z - mean) * inv, 0.f);
        float r3 = fmaxf((a.w - mean) * inv, 0.f);
        uint2 uh;
        uh.x = pack2h(r0, r1); uh.y = pack2h(r2, r3);
        uint32_t off = sw_off(row, lane >> 1) + (lane & 1) * 8;
        *reinterpret_cast<uint2*>(dst + off) = uh;
    }
}

// ---- x1 MMA: A 64-row(256B), B 128-row(256B); 4 warps 32x64
__device__ __forceinline__ void mma_mm_x1(float acc[2][8][4],
                                          uint32_t sA, uint32_t sB) {
    int lane = threadIdx.x & 31, wid = threadIdx.x >> 5;
    int wm = (wid & 1) * 32, wn = (wid >> 1) * 64;
    int rsub  = ((lane >> 3) & 1) * 8 + (lane & 7);
    int khalf = (lane >> 4) & 1;
    #pragma unroll
    for (int ks = 0; ks < 8; ks++) {
        int chunk = 2 * ks + khalf;
        uint32_t a[2][4];
        #pragma unroll
        for (int mt = 0; mt < 2; mt++)
            ldsm4(a[mt], sA + sw_off(wm + mt * 16 + rsub, chunk));
        uint32_t b[8][2];
        #pragma unroll
        for (int nt2 = 0; nt2 < 4; nt2++) {
            uint32_t r[4];
            ldsm4(r, sB + sw_off(wn + nt2 * 16 + rsub, chunk));
            b[nt2 * 2][0] = r[0]; b[nt2 * 2 + 1][0] = r[1];
            b[nt2 * 2][1] = r[2]; b[nt2 * 2 + 1][1] = r[3];
        }
        #pragma unroll
        for (int mt = 0; mt < 2; mt++)
            #pragma unroll
            for (int nt = 0; nt < 8; nt++)
                mma_f16(acc[mt][nt], a[mt], b[nt]);
    }
}

// ---- x1 MMA for S: A=Q 64-row(256B), B=K 64-row; 4 warps 32x32
__device__ __forceinline__ void mma_s_x1(float acc[2][4][4],
                                         uint32_t sA, uint32_t sB) {
    int lane = threadIdx.x & 31, wid = threadIdx.x >> 5;
    int wm = (wid & 1) * 32, wn = (wid >> 1) * 32;
    int rsub  = ((lane >> 3) & 1) * 8 + (lane & 7);
    int khalf = (lane >> 4) & 1;
    #pragma unroll
    for (int ks = 0; ks < 8; ks++) {
        int chunk = 2 * ks + khalf;
        uint32_t a[2][4];
        #pragma unroll
        for (int mt = 0; mt < 2; mt++)
            ldsm4(a[mt], sA + sw_off(wm + mt * 16 + rsub, chunk));
        uint32_t b[4][2];
        #pragma unroll
        for (int nt2 = 0; nt2 < 2; nt2++) {
            uint32_t r[4];
            ldsm4(r, sB + sw_off(wn + nt2 * 16 + rsub, chunk));
            b[nt2 * 2][0] = r[0]; b[nt2 * 2 + 1][0] = r[1];
            b[nt2 * 2][1] = r[2]; b[nt2 * 2 + 1][1] = r[3];
        }
        #pragma unroll
        for (int mt = 0; mt < 2; mt++)
            #pragma unroll
            for (int nt = 0; nt < 4; nt++)
                mma_f16(acc[mt][nt], a[mt], b[nt]);
    }
}

// ---- x1 MMA for PV: A=P, B=V-subtile (64 rows at byte offset), K=64
__device__ __forceinline__ void mma_pv_x1(float acc[2][4][4],
                                          uint32_t sA, uint32_t sB) {
    int lane = threadIdx.x & 31, wid = threadIdx.x >> 5;
    int wm = (wid & 1) * 32, wn = (wid >> 1) * 32;
    int rsub  = ((lane >> 3) & 1) * 8 + (lane & 7);
    int khalf = (lane >> 4) & 1;
    #pragma unroll
    for (int ks = 0; ks < 4; ks++) {
        int chunk = 2 * ks + khalf;
        uint32_t a[2][4];
        #pragma unroll
        for (int mt = 0; mt < 2; mt++)
            ldsm4(a[mt], sA + sw_off128(wm + mt * 16 + rsub, chunk));
        uint32_t b[4][2];
        #pragma unroll
        for (int nt2 = 0; nt2 < 2; nt2++) {
            uint32_t r[4];
            ldsm4(r, sB + sw_off128(wn + nt2 * 16 + rsub, chunk));
            b[nt2 * 2][0] = r[0]; b[nt2 * 2 + 1][0] = r[1];
            b[nt2 * 2][1] = r[2]; b[nt2 * 2 + 1][1] = r[3];
        }
        #pragma unroll
        for (int mt = 0; mt < 2; mt++)
            #pragma unroll
            for (int nt = 0; nt < 4; nt++)
                mma_f16(acc[mt][nt], a[mt], b[nt]);
    }
}

// ---------------------------------------------------------------------------
// weights -> fp16
// ---------------------------------------------------------------------------
__global__ void convert_w_kernel(const float* __restrict__ w0, const float* __restrict__ w1,
                                 const float* __restrict__ w2, const float* __restrict__ w3,
                                 __half* __restrict__ wout) {
    const float* src = (blockIdx.x == 0) ? w0 : (blockIdx.x == 1) ? w1 : (blockIdx.x == 2) ? w2 : w3;
    size_t base = (size_t)blockIdx.x * EE * EE;
    for (int i = threadIdx.x; i < EE * EE; i += blockDim.x)
        wout[base + i] = __float2half_rn(src[i]);
}

// ---------------------------------------------------------------------------
// prep: adj row -> rsqrt(deg) + 512-bit mask (16 uint32 per row)
// ---------------------------------------------------------------------------
__global__ __launch_bounds__(256) void prep_kernel(const float* __restrict__ adj,
                                                   float* __restrict__ rscale,
                                                   uint32_t* __restrict__ maskbuf) {
    int row  = blockIdx.x * 8 + (threadIdx.x >> 5);
    int lane = threadIdx.x & 31;
    const float4* p = reinterpret_cast<const float4*>(adj + (size_t)row * SS) + lane * 4;
    float s = 0.f;
    uint32_t m16 = 0;
    #pragma unroll
    for (int i = 0; i < 4; i++) {
        float4 a = p[i];
        s += a.x + a.y + a.z + a.w;
        if (a.x != 0.f) m16 |= 1u << (4 * i + 0);
        if (a.y != 0.f) m16 |= 1u << (4 * i + 1);
        if (a.z != 0.f) m16 |= 1u << (4 * i + 2);
        if (a.w != 0.f) m16 |= 1u << (4 * i + 3);
    }
    float t = s;
    #pragma unroll
    for (int o = 16; o; o >>= 1) t += __shfl_xor_sync(0xffffffffu, t, o);
    if (lane == 0) rscale[row] = rsqrtf(t);
    uint32_t lo = __shfl_sync(0xffffffffu, m16, (lane & 15) * 2);
    uint32_t hi = __shfl_sync(0xffffffffu, m16, (lane & 15) * 2 + 1);
    if (lane < 16) maskbuf[(size_t)row * 16 + lane] = lo | (hi << 16);
}

// ---------------------------------------------------------------------------
// QKV MMA (fused LN; Q pre-scaled by rsqrt(deg)): grid (1536, 3), 128 thr.
// ---------------------------------------------------------------------------
__global__ __launch_bounds__(128, 3) void mm_qkv_kernel(
    const float* __restrict__ x,
    const __half* __restrict__ wbuf,
    const float* __restrict__ bq, const float* __restrict__ bk, const float* __restrict__ bv,
    const float* __restrict__ rsp,
    __half* __restrict__ qq, __half* __restrict__ kk, __half* __restrict__ vt) {
    extern __shared__ __align__(1024) char smem[];
    uint32_t sb = smem_u32(smem);
    int tid = threadIdx.x, lane = tid & 31, wid = tid >> 5;
    int y = blockIdx.y;
    int m0 = blockIdx.x * 64;
    const float* bias = (y == 0) ? bq : (y == 1) ? bk : bv;

    cp_tile256<128>(smem + MM_W, wbuf + (size_t)y * EE * EE, EE);
    CP_COMMIT();
    ln_stage(x + (size_t)m0 * EE, smem + MM_A);  // overlaps W loads
    CP_WAIT0();
    __syncthreads();

    float acc[2][8][4];
    #pragma unroll
    for (int i = 0; i < 2; i++)
        #pragma unroll
        for (int j = 0; j < 8; j++)
            #pragma unroll
            for (int t = 0; t < 4; t++) acc[i][j][t] = 0.f;
    mma_mm_x1(acc, sb + MM_A, sb + MM_W);

    int fr = (wid & 1) * 32 + (lane >> 2);
    int fc = (wid >> 1) * 64 + ((lane & 3) << 1);

    if (y < 2) {
        __half* ob = (y == 0) ? qq : kk;
        float rsc[2][2];
        #pragma unroll
        for (int mt = 0; mt < 2; mt++)
            #pragma unroll
            for (int hh = 0; hh < 2; hh++)
                rsc[mt][hh] = (y == 0) ? rsp[m0 + fr + mt * 16 + hh * 8] : 1.0f;
        #pragma unroll
        for (int mt = 0; mt < 2; mt++) {
            #pragma unroll
            for (int nt = 0; nt < 8; nt++) {
                int c = fc + nt * 8;
                float b0 = bias[c], b1 = bias[c + 1];
                #pragma unroll
                for (int hh = 0; hh < 2; hh++) {
                    int rr = fr + mt * 16 + hh * 8;
                    float sc = rsc[mt][hh];
                    float v0 = (acc[mt][nt][hh * 2 + 0] + b0) * sc;
                    float v1 = (acc[mt][nt][hh * 2 + 1] + b1) * sc;
                    size_t off = (size_t)(m0 + rr) * EE + c;
                    *reinterpret_cast<uint32_t*>(ob + off) = pack2h(v0, v1);
                }
            }
        }
    } else {
        // V: stage transposed [f=128][m=64] fp16, then coalesced write
        __syncthreads();     // A tile reads done
        __half* sh = reinterpret_cast<__half*>(smem + MM_A);
        #pragma unroll
        for (int mt = 0; mt < 2; mt++) {
            #pragma unroll
            for (int nt = 0; nt < 8; nt++) {
                int c = fc + nt * 8;
                float b0 = bias[c], b1 = bias[c + 1];
                #pragma unroll
                for (int hh = 0; hh < 2; hh++) {
                    int rr = fr + mt * 16 + hh * 8;
                    sh[c * 64 + rr]       = __float2half_rn(acc[mt][nt][hh * 2 + 0] + b0);
                    sh[(c + 1) * 64 + rr] = __float2half_rn(acc[mt][nt][hh * 2 + 1] + b1);
                }
            }
        }
        __syncthreads();
        int b = m0 >> 9;
        int kbase = m0 & 511;
        #pragma unroll
        for (int it = 0; it < 8; it++) {
            int idx = tid + it * 128;
            int f = idx >> 3, ch = idx & 7;
            uint4 vh = *reinterpret_cast<uint4*>(sh + f * 64 + ch * 8);
            size_t off = ((size_t)b * EE + f) * SS + kbase + ch * 8;
            *reinterpret_cast<uint4*>(vt + off) = vh;
        }
    }
}

// ---------------------------------------------------------------------------
// FUSED flash attention (fp16 x1), full-V tile, 3 CTAs/SM target:
// grid (8 qt, 192 b), 128 threads.
// ---------------------------------------------------------------------------
__global__ __launch_bounds__(128, 3) void fused_attn_kernel(
    const __half* __restrict__ qp, const __half* __restrict__ kp,
    const __half* __restrict__ vtp,
    const uint32_t* __restrict__ maskbuf,
    float* __restrict__ attf) {
    extern __shared__ __align__(1024) char smem[];
    uint32_t sb = smem_u32(smem);
    int tid = threadIdx.x, lane = tid & 31, wid = tid >> 5;
    int qt = blockIdx.x, b = blockIdx.y;
    size_t ar = (size_t)b * SS + qt * 64;

    float* pmax = reinterpret_cast<float*>(smem + F_STAT);      // [2][64]
    float* psum = pmax + 128;                                   // [2][64]

    // prologue: Q, K(0), V(0) full 128 f-rows x 64 k
    cp_tile256<64>(smem + F_Q, qp + ar * EE, EE);
    cp_tile256<64>(smem + F_K, kp + (size_t)b * SS * EE, EE);
    cp_tile128<128>(smem + F_V, vtp + (size_t)b * EE * SS, SS);
    CP_COMMIT();

    int wm = (wid & 1) * 32, wns = (wid >> 1) * 32, wni = wid >> 1;
    int fr = wm + (lane >> 2);
    int fcl = (lane & 3) << 1;

    float mrow[4], lrow[4];
    #pragma unroll
    for (int ri = 0; ri < 4; ri++) { mrow[ri] = -1e30f; lrow[ri] = 0.f; }
    float O[2][2][4][4];    // [f-half][mt][nt][e]
    #pragma unroll
    for (int h = 0; h < 2; h++)
        #pragma unroll
        for (int i = 0; i < 2; i++)
            #pragma unroll
            for (int j = 0; j < 4; j++)
                #pragma unroll
                for (int t = 0; t < 4; t++) O[h][i][j][t] = 0.f;

    const uint2* mb2 = reinterpret_cast<const uint2*>(maskbuf);

    for (int kc = 0; kc < 8; kc++) {
        CP_WAIT0();          // K(kc) + V(kc) arrived
        __syncthreads();

        float S[2][4][4];
        #pragma unroll
        for (int i = 0; i < 2; i++)
            #pragma unroll
            for (int j = 0; j < 4; j++)
                #pragma unroll
                for (int t = 0; t < 4; t++) S[i][j][t] = 0.f;
        mma_s_x1(S, sb + F_Q, sb + F_K);
        __syncthreads();     // K buffer reads done

        // prefetch K(kc+1) while softmax runs
        if (kc < 7) {
            cp_tile256<64>(smem + F_K, kp + ((size_t)b * SS + (kc + 1) * 64) * EE, EE);
            CP_COMMIT();
        }

        uint32_t mw[4][2];
        #pragma unroll
        for (int ri = 0; ri < 4; ri++) {
            int lr = fr + (ri >> 1) * 16 + (ri & 1) * 8;
            uint2 mv = mb2[(ar + lr) * 8 + kc];
            mw[ri][0] = mv.x; mw[ri][1] = mv.y;
        }

        // masked per-thread max
        float cmax[4] = { -1e30f, -1e30f, -1e30f, -1e30f };
        #pragma unroll
        for (int mt = 0; mt < 2; mt++)
            #pragma unroll
            for (int hh = 0; hh < 2; hh++) {
                int ri = mt * 2 + hh;
                #pragma unroll
                for (int nt = 0; nt < 4; nt++) {
                    int c0 = wns + fcl + nt * 8;
                    uint32_t w = mw[ri][c0 >> 5];
                    int bit = c0 & 31;
                    if ((w >> bit) & 1u)       cmax[ri] = fmaxf(cmax[ri], S[mt][nt][hh * 2 + 0]);
                    if ((w >> (bit + 1)) & 1u) cmax[ri] = fmaxf(cmax[ri], S[mt][nt][hh * 2 + 1]);
                }
            }
        #pragma unroll
        for (int ri = 0; ri < 4; ri++) {
            cmax[ri] = fmaxf(cmax[ri], __shfl_xor_sync(0xffffffffu, cmax[ri], 1));
            cmax[ri] = fmaxf(cmax[ri], __shfl_xor_sync(0xffffffffu, cmax[ri], 2));
        }
        if ((lane & 3) == 0) {
            #pragma unroll
            for (int ri = 0; ri < 4; ri++) {
                int lr = fr + (ri >> 1) * 16 + (ri & 1) * 8;
                pmax[wni * 64 + lr] = cmax[ri];
            }
        }
        __syncthreads();

        float fscale[4], mn[4];
        #pragma unroll
        for (int ri = 0; ri < 4; ri++) {
            int lr = fr + (ri >> 1) * 16 + (ri & 1) * 8;
            float cm = fmaxf(pmax[lr], pmax[64 + lr]);
            mn[ri] = fmaxf(mrow[ri], cm);
            fscale[ri] = __expf(mrow[ri] - mn[ri]);
            mrow[ri] = mn[ri];
        }

        // exp + write P (fp16) + partial sums
        float csum[4] = { 0.f, 0.f, 0.f, 0.f };
        #pragma unroll
        for (int mt = 0; mt < 2; mt++)
            #pragma unroll
            for (int hh = 0; hh < 2; hh++) {
                int ri = mt * 2 + hh;
                int lr = fr + mt * 16 + hh * 8;
                #pragma unroll
                for (int nt = 0; nt < 4; nt++) {
                    int c0 = wns + fcl + nt * 8;
                    uint32_t w = mw[ri][c0 >> 5];
                    int bit = c0 & 31;
                    float p0 = ((w >> bit) & 1u)       ? __expf(S[mt][nt][hh * 2 + 0] - mn[ri]) : 0.f;
                    float p1 = ((w >> (bit + 1)) & 1u) ? __expf(S[mt][nt][hh * 2 + 1] - mn[ri]) : 0.f;
                    csum[ri] += p0 + p1;
                    uint32_t off = sw_off128(lr, c0 >> 3) + (c0 & 7) * 2;
                    *reinterpret_cast<uint32_t*>(smem + F_P + off) = pack2h(p0, p1);
                }
            }
        #pragma unroll
        for (int ri = 0; ri < 4; ri++) {
            csum[ri] += __shfl_xor_sync(0xffffffffu, csum[ri], 1);
            csum[ri] += __shfl_xor_sync(0xffffffffu, csum[ri], 2);
        }
        if ((lane & 3) == 0) {
            #pragma unroll
            for (int ri = 0; ri < 4; ri++) {
                int lr = fr + (ri >> 1) * 16 + (ri & 1) * 8;
                psum[wni * 64 + lr] = csum[ri];
            }
        }
        __syncthreads();     // P + psum visible

        #pragma unroll
        for (int ri = 0; ri < 4; ri++) {
            int lr = fr + (ri >> 1) * 16 + (ri & 1) * 8;
            lrow[ri] = lrow[ri] * fscale[ri] + psum[lr] + psum[64 + lr];
        }
        #pragma unroll
        for (int mt = 0; mt < 2; mt++)
            #pragma unroll
            for (int hh = 0; hh < 2; hh++) {
                float f = fscale[mt * 2 + hh];
                #pragma unroll
                for (int h = 0; h < 2; h++)
                    #pragma unroll
                    for (int nt = 0; nt < 4; nt++) {
                        O[h][mt][nt][hh * 2 + 0] *= f;
                        O[h][mt][nt][hh * 2 + 1] *= f;
                    }
            }

        // PV both f-halves back-to-back (V tile holds all 128 f-rows)
        mma_pv_x1(O[0], sb + F_P, sb + F_V);
        mma_pv_x1(O[1], sb + F_P, sb + F_V + 8192);
        __syncthreads();     // P + V buffers free

        if (kc < 7) {
            cp_tile128<128>(smem + F_V, vtp + (size_t)b * EE * SS + (kc + 1) * 64, SS);
            CP_COMMIT();
        }
    }

    // epilogue: normalize + store
    #pragma unroll
    for (int mt = 0; mt < 2; mt++)
        #pragma unroll
        for (int hh = 0; hh < 2; hh++) {
            int ri = mt * 2 + hh;
            float inv = 1.f / lrow[ri];
            size_t gm = ar + fr + mt * 16 + hh * 8;
            #pragma unroll
            for (int h = 0; h < 2; h++)
                #pragma unroll
                for (int nt = 0; nt < 4; nt++) {
                    int c = h * 64 + wns + fcl + nt * 8;
                    *reinterpret_cast<float2*>(attf + gm * EE + c) =
                        make_float2(O[h][mt][nt][hh * 2 + 0] * inv,
                                    O[h][mt][nt][hh * 2 + 1] * inv);
                }
        }
}

// ---------------------------------------------------------------------------
// out projection (fused LN, fp16 x1): out = x + LN_ReLU(attf) @ Wo^T + bo.
// ---------------------------------------------------------------------------
__global__ __launch_bounds__(128, 3) void mm_out_kernel(
    const float* __restrict__ attf,
    const __half* __restrict__ wo,
    const float* __restrict__ bo, const float* __restrict__ x,
    float* __restrict__ out) {
    extern __shared__ __align__(1024) char smem[];
    uint32_t sb = smem_u32(smem);
    int tid = threadIdx.x, lane = tid & 31, wid = tid >> 5;
    int m0 = blockIdx.x * 64;

    cp_tile256<128>(smem + MM_W, wo, EE);
    CP_COMMIT();
    ln_stage(attf + (size_t)m0 * EE, smem + MM_A);
    CP_WAIT0();
    __syncthreads();

    float acc[2][8][4];
    #pragma unroll
    for (int i = 0; i < 2; i++)
        #pragma unroll
        for (int j = 0; j < 8; j++)
            #pragma unroll
            for (int t = 0; t < 4; t++) acc[i][j][t] = 0.f;
    mma_mm_x1(acc, sb + MM_A, sb + MM_W);

    int fr = (wid & 1) * 32 + (lane >> 2);
    int fc = (wid >> 1) * 64 + ((lane & 3) << 1);
    #pragma unroll
    for (int mt = 0; mt < 2; mt++) {
        #pragma unroll
        for (int hh = 0; hh < 2; hh++) {
            size_t gm = (size_t)(m0 + fr + mt * 16 + hh * 8);
            #pragma unroll
            for (int nt = 0; nt < 8; nt++) {
                int c = fc + nt * 8;
                float2 xr = *reinterpret_cast<const float2*>(x + gm * EE + c);
                float v0 = acc[mt][nt][hh * 2 + 0] + bo[c] + xr.x;
                float v1 = acc[mt][nt][hh * 2 + 1] + bo[c + 1] + xr.y;
                *reinterpret_cast<float2*>(out + gm * EE + c) = make_float2(v0, v1);
            }
        }
    }
}

// ---------------------------------------------------------------------------
extern "C" void kernel_launch(void* const* d_in, const int* in_sizes, int n_in,
                              void* d_out, int out_size) {
    const float* x   = (const float*)d_in[0];
    const float* adj = (const float*)d_in[1];
    const float* Wq  = (const float*)d_in[2];
    const float* bq  = (const float*)d_in[3];
    const float* Wk  = (const float*)d_in[4];
    const float* bk  = (const float*)d_in[5];
    const float* Wv  = (const float*)d_in[6];
    const float* bv  = (const float*)d_in[7];
    const float* Wo  = (const float*)d_in[8];
    const float* bo  = (const float*)d_in[9];
    float* out = (float*)d_out;

    char* s = nullptr;
    cudaGetSymbolAddress((void**)&s, g_scratch);
    __half* qbuf = (__half*)(s + O_Q);
    __half* kbuf = (__half*)(s + O_K);
    __half* vt   = (__half*)(s + O_VT);
    float*  attf = (float*)(s + O_ATTO);
    __half* wbuf = (__half*)(s + O_W);
    float*  rs   = (float*)(s + O_RS);
    uint32_t* mb = (uint32_t*)(s + O_MB);

    cudaFuncSetAttribute(mm_qkv_kernel,     cudaFuncAttributeMaxDynamicSharedMemorySize, MM_SMEM);
    cudaFuncSetAttribute(fused_attn_kernel, cudaFuncAttributeMaxDynamicSharedMemorySize, F_SMEM);
    cudaFuncSetAttribute(mm_out_kernel,     cudaFuncAttributeMaxDynamicSharedMemorySize, MM_SMEM);

    convert_w_kernel<<<4, 256>>>(Wq, Wk, Wv, Wo, wbuf);
    prep_kernel<<<NROWS / 8, 256>>>(adj, rs, mb);
    mm_qkv_kernel<<<dim3(NROWS / 64, 3), 128, MM_SMEM>>>(
        x, wbuf, bq, bk, bv, rs, qbuf, kbuf, vt);
    fused_attn_kernel<<<dim3(8, NB), 128, F_SMEM>>>(
        qbuf, kbuf, vt, mb, attf);
    mm_out_kernel<<<NROWS / 64, 128, MM_SMEM>>>(
        attf, wbuf + 3 * EE * EE, bo, x, out);
}